// round 9
// baseline (speedup 1.0000x reference)
#include <cuda_runtime.h>
#include <cuda_bf16.h>
#include <cstdint>
#include <cstddef>

// ---------------------------------------------------------------------------
// Problem constants
// ---------------------------------------------------------------------------
#define B_SZ   2
#define S_SZ   4096
#define HID    2048
#define NH     32
#define HD     64
#define NHD    2048
#define M_ROWS (B_SZ * S_SZ)       // 8192
#define NT     32
#define NKV    4
#define SCALE_F 0.125f
#define KDIM   2048

// ---------------------------------------------------------------------------
// PTX helpers (plain sm_80+ features only)
// ---------------------------------------------------------------------------
__device__ __forceinline__ uint32_t smem_u32(const void* p) {
    uint32_t a;
    asm("{ .reg .u64 t; cvta.to.shared.u64 t, %1; cvt.u32.u64 %0, t; }" : "=r"(a) : "l"(p));
    return a;
}
#define CP_ASYNC16(dst, src) \
    asm volatile("cp.async.cg.shared.global [%0], [%1], 16;" :: "r"(dst), "l"(src) : "memory")
#define CP_COMMIT()  asm volatile("cp.async.commit_group;" ::: "memory")
#define CP_WAIT(n)   asm volatile("cp.async.wait_group %0;" :: "n"(n) : "memory")

__device__ __forceinline__ void ldm4(uint32_t* r, uint32_t addr) {
    asm volatile("ldmatrix.sync.aligned.m8n8.x4.shared.b16 {%0,%1,%2,%3}, [%4];"
        : "=r"(r[0]), "=r"(r[1]), "=r"(r[2]), "=r"(r[3]) : "r"(addr));
}
__device__ __forceinline__ void ldm4t(uint32_t* r, uint32_t addr) {
    asm volatile("ldmatrix.sync.aligned.m8n8.x4.trans.shared.b16 {%0,%1,%2,%3}, [%4];"
        : "=r"(r[0]), "=r"(r[1]), "=r"(r[2]), "=r"(r[3]) : "r"(addr));
}
__device__ __forceinline__ void mma_bf16(float* d, const uint32_t* a, uint32_t b0, uint32_t b1) {
    asm volatile("mma.sync.aligned.m16n8k16.row.col.f32.bf16.bf16.f32 "
        "{%0,%1,%2,%3}, {%4,%5,%6,%7}, {%8,%9}, {%0,%1,%2,%3};"
        : "+f"(d[0]), "+f"(d[1]), "+f"(d[2]), "+f"(d[3])
        : "r"(a[0]), "r"(a[1]), "r"(a[2]), "r"(a[3]), "r"(b0), "r"(b1));
}
__device__ __forceinline__ uint32_t pkbf(float a, float b) {
    __nv_bfloat162 t(__float2bfloat16(a), __float2bfloat16(b));
    return *(uint32_t*)&t;
}

// ---------------------------------------------------------------------------
// Scratch (device globals)
// ---------------------------------------------------------------------------
__device__ __nv_bfloat16 g_hshi[M_ROWS * HID];
__device__ __nv_bfloat16 g_hslo[M_ROWS * HID];
__device__ __nv_bfloat16 g_wthi[4 * HID * NHD];
__device__ __nv_bfloat16 g_wtlo[4 * HID * NHD];
__device__ __nv_bfloat16 g_qhi[M_ROWS * NHD];
__device__ __nv_bfloat16 g_qlo[M_ROWS * NHD];
__device__ __nv_bfloat16 g_khi[M_ROWS * NHD];
__device__ __nv_bfloat16 g_klo[M_ROWS * NHD];
__device__ __nv_bfloat16 g_vhi[M_ROWS * NHD];
__device__ __nv_bfloat16 g_vlo[M_ROWS * NHD];
__device__ __nv_bfloat16 g_atthi[M_ROWS * NHD];
__device__ __nv_bfloat16 g_attlo[M_ROWS * NHD];

// ---------------------------------------------------------------------------
// Pre-pass 1: elementwise fp32 -> (hi, lo) bf16 split
// ---------------------------------------------------------------------------
__global__ void split_kernel(const float* __restrict__ x,
                             __nv_bfloat16* __restrict__ hi,
                             __nv_bfloat16* __restrict__ lo, int n4)
{
    int i = blockIdx.x * blockDim.x + threadIdx.x;
    if (i >= n4) return;
    const float4 v = ((const float4*)x)[i];
    __nv_bfloat16 h0 = __float2bfloat16(v.x), h1 = __float2bfloat16(v.y);
    __nv_bfloat16 h2 = __float2bfloat16(v.z), h3 = __float2bfloat16(v.w);
    __nv_bfloat16 l0 = __float2bfloat16(v.x - __bfloat162float(h0));
    __nv_bfloat16 l1 = __float2bfloat16(v.y - __bfloat162float(h1));
    __nv_bfloat16 l2 = __float2bfloat16(v.z - __bfloat162float(h2));
    __nv_bfloat16 l3 = __float2bfloat16(v.w - __bfloat162float(h3));
    ((__nv_bfloat162*)hi)[i * 2]     = __nv_bfloat162(h0, h1);
    ((__nv_bfloat162*)hi)[i * 2 + 1] = __nv_bfloat162(h2, h3);
    ((__nv_bfloat162*)lo)[i * 2]     = __nv_bfloat162(l0, l1);
    ((__nv_bfloat162*)lo)[i * 2 + 1] = __nv_bfloat162(l2, l3);
}

// ---------------------------------------------------------------------------
// Pre-pass 2: W[K,N] -> Wt[N,K] with bf16 hi/lo split
// ---------------------------------------------------------------------------
__global__ void wsplit_kernel(const float* __restrict__ W0, const float* __restrict__ W1,
                              const float* __restrict__ W2, const float* __restrict__ W3,
                              __nv_bfloat16* __restrict__ hi, __nv_bfloat16* __restrict__ lo)
{
    const int z = blockIdx.z;
    const float* W = (z == 0) ? W0 : (z == 1) ? W1 : (z == 2) ? W2 : W3;
    __shared__ float t[32][33];
    const int n0 = blockIdx.x * 32, k0 = blockIdx.y * 32;
    const int tx = threadIdx.x, ty = threadIdx.y;
#pragma unroll
    for (int i = 0; i < 4; i++)
        t[ty + 8 * i][tx] = W[(size_t)(k0 + ty + 8 * i) * NHD + n0 + tx];
    __syncthreads();
    const size_t zo = (size_t)z * HID * NHD;
#pragma unroll
    for (int i = 0; i < 4; i++) {
        const float x = t[tx][ty + 8 * i];
        const __nv_bfloat16 h = __float2bfloat16(x);
        const __nv_bfloat16 l = __float2bfloat16(x - __bfloat162float(h));
        const size_t o = zo + (size_t)(n0 + ty + 8 * i) * KDIM + k0 + tx;
        hi[o] = h;
        lo[o] = l;
    }
}

// ---------------------------------------------------------------------------
// Split-bf16 HMMA GEMM (exact R7 best config): CTA 128x128, 4 warps (64x64),
// BK=32, 2-stage cp.async double buffer, 80KB smem -> 2 CTAs/SM.
// ---------------------------------------------------------------------------
#define BK        32
#define NITER     (KDIM / BK)           // 64
#define STR_B     80
#define MAT_B     (128 * STR_B)         // 10240
#define OFF_AH    0
#define OFF_AL    MAT_B
#define OFF_BH    (2 * MAT_B)
#define OFF_BL    (3 * MAT_B)
#define STAGE_B   (4 * MAT_B)           // 40960
#define GEMM_SMEM (2 * STAGE_B)         // 81920

struct GemmPtrs {
    const __nv_bfloat16 *Ahi, *Alo, *Bhi, *Blo;
    float* C;
    __nv_bfloat16 *Chi, *Clo;
};

__device__ __forceinline__ void gemm_copy_stage(
    uint32_t sdst, const GemmPtrs& g, int m0, int n0, int kb, int tid)
{
#pragma unroll
    for (int i = 0; i < 16; i++) {
        const int idx = tid + i * 128;
        const int mat = idx >> 9, rem = idx & 511;
        const int row = rem >> 2, c = rem & 3;
        const __nv_bfloat16* sp;
        if (mat == 0)      sp = g.Ahi + (size_t)(m0 + row) * KDIM + kb + c * 8;
        else if (mat == 1) sp = g.Alo + (size_t)(m0 + row) * KDIM + kb + c * 8;
        else if (mat == 2) sp = g.Bhi + (size_t)(n0 + row) * KDIM + kb + c * 8;
        else               sp = g.Blo + (size_t)(n0 + row) * KDIM + kb + c * 8;
        CP_ASYNC16(sdst + mat * MAT_B + row * STR_B + c * 16, sp);
    }
    CP_COMMIT();
}

template <bool SPLIT>
__device__ __forceinline__ void gemm_body_mma(const GemmPtrs& g)
{
    extern __shared__ __align__(128) char smem[];
    const uint32_t sbase = smem_u32(smem);
    const int tid = threadIdx.x, wid = tid >> 5, lane = tid & 31;
    const int m0 = blockIdx.y * 128, n0 = blockIdx.x * 128;
    const int wm = wid & 1, wn = wid >> 1;

    float acc[4][8][4];
#pragma unroll
    for (int a = 0; a < 4; a++)
#pragma unroll
        for (int b = 0; b < 8; b++)
#pragma unroll
            for (int c = 0; c < 4; c++) acc[a][b][c] = 0.f;

    const uint32_t lofs = (uint32_t)((lane & 15) * STR_B + (lane >> 4) * 16);

    gemm_copy_stage(sbase, g, m0, n0, 0, tid);

    for (int t = 0; t < NITER; ++t) {
        if (t + 1 < NITER) {
            gemm_copy_stage(sbase + ((t + 1) & 1) * STAGE_B, g, m0, n0, (t + 1) * BK, tid);
            CP_WAIT(1);
        } else {
            CP_WAIT(0);
        }
        __syncthreads();

        const uint32_t s0 = sbase + (t & 1) * STAGE_B;
#pragma unroll
        for (int ks = 0; ks < 2; ++ks) {
            const uint32_t aoff = s0 + OFF_AH + (uint32_t)(wm * 64 * STR_B + ks * 32) + lofs;
            uint32_t Ah[16], Al[16];
#pragma unroll
            for (int mf = 0; mf < 4; mf++) {
                ldm4(Ah + mf * 4, aoff + mf * 16 * STR_B);
                ldm4(Al + mf * 4, aoff + (OFF_AL - OFF_AH) + mf * 16 * STR_B);
            }
#pragma unroll
            for (int half = 0; half < 2; half++) {
                const uint32_t boff = s0 + OFF_BH +
                    (uint32_t)((wn * 64 + half * 32) * STR_B + ks * 32) + lofs;
                uint32_t Bh[8], Bl[8];
                ldm4(Bh + 0, boff);
                ldm4(Bh + 4, boff + 16 * STR_B);
                ldm4(Bl + 0, boff + (OFF_BL - OFF_BH));
                ldm4(Bl + 4, boff + (OFF_BL - OFF_BH) + 16 * STR_B);
#pragma unroll
                for (int mf = 0; mf < 4; mf++)
#pragma unroll
                    for (int nl = 0; nl < 4; nl++) {
                        float* d = acc[mf][half * 4 + nl];
                        const uint32_t b0i = (nl >> 1) * 4 + (nl & 1);
                        mma_bf16(d, Ah + mf * 4, Bh[b0i], Bh[b0i + 2]);
                        mma_bf16(d, Ah + mf * 4, Bl[b0i], Bl[b0i + 2]);
                        mma_bf16(d, Al + mf * 4, Bh[b0i], Bh[b0i + 2]);
                    }
            }
        }
        __syncthreads();
    }

    const int gq = lane >> 2, tig = lane & 3;
#pragma unroll
    for (int mf = 0; mf < 4; mf++) {
        const int row = m0 + wm * 64 + mf * 16 + gq;
#pragma unroll
        for (int nf = 0; nf < 8; nf++) {
            const int col = n0 + wn * 64 + nf * 8 + tig * 2;
            if (SPLIT) {
#pragma unroll
                for (int half = 0; half < 2; half++) {
                    const size_t off = (size_t)(row + half * 8) * 2048 + col;
                    const float x0 = acc[mf][nf][half * 2], x1 = acc[mf][nf][half * 2 + 1];
                    const __nv_bfloat16 h0 = __float2bfloat16(x0), h1 = __float2bfloat16(x1);
                    const __nv_bfloat16 l0 = __float2bfloat16(x0 - __bfloat162float(h0));
                    const __nv_bfloat16 l1 = __float2bfloat16(x1 - __bfloat162float(h1));
                    *(__nv_bfloat162*)&g.Chi[off] = __nv_bfloat162(h0, h1);
                    *(__nv_bfloat162*)&g.Clo[off] = __nv_bfloat162(l0, l1);
                }
            } else {
                *(float2*)&g.C[(size_t)row * 2048 + col] =
                    make_float2(acc[mf][nf][0], acc[mf][nf][1]);
                *(float2*)&g.C[(size_t)(row + 8) * 2048 + col] =
                    make_float2(acc[mf][nf][2], acc[mf][nf][3]);
            }
        }
    }
}

__global__ __launch_bounds__(128, 2) void qkv_mma_kernel(
    const __nv_bfloat16* __restrict__ Ahi, const __nv_bfloat16* __restrict__ Alo,
    const __nv_bfloat16* __restrict__ Whi, const __nv_bfloat16* __restrict__ Wlo,
    __nv_bfloat16* __restrict__ Qh, __nv_bfloat16* __restrict__ Ql,
    __nv_bfloat16* __restrict__ Kh, __nv_bfloat16* __restrict__ Kl,
    __nv_bfloat16* __restrict__ Vh, __nv_bfloat16* __restrict__ Vl)
{
    const size_t WSZ = (size_t)HID * NHD;
    const int z = blockIdx.z;
    GemmPtrs g;
    g.Ahi = Ahi; g.Alo = Alo;
    g.Bhi = Whi + (size_t)z * WSZ; g.Blo = Wlo + (size_t)z * WSZ;
    g.C = nullptr;
    g.Chi = (z == 0) ? Qh : (z == 1) ? Kh : Vh;
    g.Clo = (z == 0) ? Ql : (z == 1) ? Kl : Vl;
    gemm_body_mma<true>(g);
}

__global__ __launch_bounds__(128, 2) void out_mma_kernel(
    const __nv_bfloat16* __restrict__ Ahi, const __nv_bfloat16* __restrict__ Alo,
    const __nv_bfloat16* __restrict__ Whi, const __nv_bfloat16* __restrict__ Wlo,
    float* __restrict__ C)
{
    GemmPtrs g;
    g.Ahi = Ahi; g.Alo = Alo; g.Bhi = Whi; g.Blo = Wlo;
    g.C = C; g.Chi = nullptr; g.Clo = nullptr;
    gemm_body_mma<false>(g);
}

// ---------------------------------------------------------------------------
// Tensor-core flash attention (split-bf16, 3 products), 256 threads,
// K/V tiles DOUBLE-BUFFERED: copy for tile w+1 overlaps compute of tile w.
// Smem: Q 36KB + 2 x 72KB KV stages = 180KB (1 CTA/SM; reg-limited anyway).
// ---------------------------------------------------------------------------
#define ASTRB   144
#define AQH     0
#define AQL     18432
#define AKV     36864
#define KVSTG   73728
#define KH_O    0
#define KL_O    18432
#define VH_O    36864
#define VL_O    55296
#define ATT_SMEM (AKV + 2 * KVSTG)      // 184320

__device__ __forceinline__ int token_of(int tile, int jj)
{
    return ((tile >> 2) << 9) + ((jj >> 4) << 6) + ((tile & 3) << 4) + (jj & 15);
}

__device__ __forceinline__ void attn_copy_kv(
    uint32_t sstage, int kt, size_t base,
    const __nv_bfloat16* __restrict__ Khi, const __nv_bfloat16* __restrict__ Klo,
    const __nv_bfloat16* __restrict__ Vhi, const __nv_bfloat16* __restrict__ Vlo,
    int tid)
{
#pragma unroll
    for (int i = 0; i < 16; i++) {
        const int idx = tid + i * 256;
        const int mat = idx >> 10, rem = idx & 1023;
        const int row = rem >> 3, c = rem & 7;
        const int ks = token_of(kt, row);
        const size_t off = base + (size_t)ks * NHD + c * 8;
        const __nv_bfloat16* src =
            (mat == 0) ? Khi + off : (mat == 1) ? Klo + off :
            (mat == 2) ? Vhi + off : Vlo + off;
        const uint32_t doff = (mat == 0) ? KH_O : (mat == 1) ? KL_O :
                              (mat == 2) ? VH_O : VL_O;
        CP_ASYNC16(sstage + doff + row * ASTRB + c * 16, src);
    }
    CP_COMMIT();
}

__global__ __launch_bounds__(256, 1) void attn_mma_kernel(
    const __nv_bfloat16* __restrict__ Qhi, const __nv_bfloat16* __restrict__ Qlo,
    const __nv_bfloat16* __restrict__ Khi, const __nv_bfloat16* __restrict__ Klo,
    const __nv_bfloat16* __restrict__ Vhi, const __nv_bfloat16* __restrict__ Vlo,
    __nv_bfloat16* __restrict__ Ohi, __nv_bfloat16* __restrict__ Olo)
{
    extern __shared__ __align__(128) char smem[];
    const uint32_t sbase = smem_u32(smem);
    const int t = blockIdx.x, h = blockIdx.y, b = blockIdx.z;
    const int tid = threadIdx.x, w = tid >> 5, lane = tid & 31;
    const size_t base = (size_t)b * S_SZ * NHD + (size_t)h * HD;

    const int tr = t >> 2, tc = t & 3;
    const int cr = min(max(tr, 1), 7);
    const int cc = min(max(tc, 1), 3);
    int kts[NKV];
    kts[0] = (cr - 1) * 4 + (cc - 1);
    kts[1] = (cr - 1) * 4 + cc;
    kts[2] = cr * 4 + (cc - 1);
    kts[3] = cr * 4 + cc;

    // Q tiles (hi/lo) -> smem (group 0)
    for (int i = tid; i < 2048; i += 256) {
        const int mat = i >> 10, rem = i & 1023;
        const int row = rem >> 3, c = rem & 7;
        const int qs = token_of(t, row);
        const __nv_bfloat16* src = (mat ? Qlo : Qhi) + base + (size_t)qs * NHD + c * 8;
        CP_ASYNC16(sbase + (mat ? AQL : AQH) + row * ASTRB + c * 16, src);
    }
    CP_COMMIT();

    // KV tile 0 -> stage 0 (group 1), in flight behind Q
    attn_copy_kv(sbase + AKV, kts[0], base, Khi, Klo, Vhi, Vlo, tid);

    CP_WAIT(1);          // Q complete (KV0 may still be in flight)
    __syncthreads();

    // Q fragments in registers for the whole kernel
    uint32_t qh[4][4], ql[4][4];
    const uint32_t qoff = (uint32_t)((w * 16 + (lane & 15)) * ASTRB + (lane >> 4) * 16);
#pragma unroll
    for (int kf = 0; kf < 4; kf++) {
        ldm4(qh[kf], sbase + AQH + qoff + kf * 32);
        ldm4(ql[kf], sbase + AQL + qoff + kf * 32);
    }

    float O[8][4];
#pragma unroll
    for (int nf = 0; nf < 8; nf++)
#pragma unroll
        for (int c = 0; c < 4; c++) O[nf][c] = 0.f;
    float m0 = -1e30f, m1 = -1e30f, l0 = 0.f, l1 = 0.f;

    for (int w4 = 0; w4 < NKV; ++w4) {
        // Prefetch tile w4+1 into the other stage; overlaps this tile's compute.
        // Stage (w4+1)&1 was last read in tile w4-1 (trailing sync passed).
        if (w4 + 1 < NKV) {
            attn_copy_kv(sbase + AKV + ((w4 + 1) & 1) * KVSTG, kts[w4 + 1],
                         base, Khi, Klo, Vhi, Vlo, tid);
            CP_WAIT(1);      // tile w4 complete; w4+1 in flight
        } else {
            CP_WAIT(0);
        }
        __syncthreads();

        const uint32_t sstage = sbase + AKV + (w4 & 1) * KVSTG;

        // ---- S = Q @ K^T (3-product split), 128 keys ----
        float S[16][4];
#pragma unroll
        for (int nf = 0; nf < 16; nf++)
#pragma unroll
            for (int c = 0; c < 4; c++) S[nf][c] = 0.f;

#pragma unroll
        for (int kf = 0; kf < 4; kf++) {
#pragma unroll
            for (int g = 0; g < 8; g++) {
                uint32_t kh[4], kl[4];
                const uint32_t ko = (uint32_t)((g * 16 + (lane & 15)) * ASTRB +
                                               (lane >> 4) * 16 + kf * 32);
                ldm4(kh, sstage + KH_O + ko);
                mma_bf16(S[2 * g],     qh[kf], kh[0], kh[2]);
                mma_bf16(S[2 * g + 1], qh[kf], kh[1], kh[3]);
                ldm4(kl, sstage + KL_O + ko);
                mma_bf16(S[2 * g],     qh[kf], kl[0], kl[2]);
                mma_bf16(S[2 * g + 1], qh[kf], kl[1], kl[3]);
                mma_bf16(S[2 * g],     ql[kf], kh[0], kh[2]);
                mma_bf16(S[2 * g + 1], ql[kf], kh[1], kh[3]);
            }
        }

        // ---- online softmax ----
        float tmax0 = -1e30f, tmax1 = -1e30f;
#pragma unroll
        for (int nf = 0; nf < 16; nf++) {
            S[nf][0] *= SCALE_F; S[nf][1] *= SCALE_F;
            S[nf][2] *= SCALE_F; S[nf][3] *= SCALE_F;
            tmax0 = fmaxf(tmax0, fmaxf(S[nf][0], S[nf][1]));
            tmax1 = fmaxf(tmax1, fmaxf(S[nf][2], S[nf][3]));
        }
        tmax0 = fmaxf(tmax0, __shfl_xor_sync(0xFFFFFFFF, tmax0, 1));
        tmax0 = fmaxf(tmax0, __shfl_xor_sync(0xFFFFFFFF, tmax0, 2));
        tmax1 = fmaxf(tmax1, __shfl_xor_sync(0xFFFFFFFF, tmax1, 1));
        tmax1 = fmaxf(tmax1, __shfl_xor_sync(0xFFFFFFFF, tmax1, 2));

        const float mn0 = fmaxf(m0, tmax0), mn1 = fmaxf(m1, tmax1);
        const float a0 = __expf(m0 - mn0), a1 = __expf(m1 - mn1);
        m0 = mn0; m1 = mn1;
        l0 *= a0; l1 *= a1;
#pragma unroll
        for (int nf = 0; nf < 8; nf++) {
            O[nf][0] *= a0; O[nf][1] *= a0;
            O[nf][2] *= a1; O[nf][3] *= a1;
        }
        float ls0 = 0.f, ls1 = 0.f;
#pragma unroll
        for (int nf = 0; nf < 16; nf++) {
            S[nf][0] = __expf(S[nf][0] - m0); ls0 += S[nf][0];
            S[nf][1] = __expf(S[nf][1] - m0); ls0 += S[nf][1];
            S[nf][2] = __expf(S[nf][2] - m1); ls1 += S[nf][2];
            S[nf][3] = __expf(S[nf][3] - m1); ls1 += S[nf][3];
        }
        l0 += ls0; l1 += ls1;

        // ---- O += P @ V; P hi via truncation-mask (exact residual) ----
#pragma unroll
        for (int kf = 0; kf < 8; kf++) {
            uint32_t ph[4], pl[4];
            {
                const float* sA = S[2 * kf];
                const float* sB = S[2 * kf + 1];
                const uint32_t uA0 = __float_as_uint(sA[0]), uA1 = __float_as_uint(sA[1]);
                const uint32_t uA2 = __float_as_uint(sA[2]), uA3 = __float_as_uint(sA[3]);
                const uint32_t uB0 = __float_as_uint(sB[0]), uB1 = __float_as_uint(sB[1]);
                const uint32_t uB2 = __float_as_uint(sB[2]), uB3 = __float_as_uint(sB[3]);
                ph[0] = __byte_perm(uA0, uA1, 0x7632);
                ph[1] = __byte_perm(uA2, uA3, 0x7632);
                ph[2] = __byte_perm(uB0, uB1, 0x7632);
                ph[3] = __byte_perm(uB2, uB3, 0x7632);
                pl[0] = pkbf(sA[0] - __uint_as_float(uA0 & 0xFFFF0000u),
                             sA[1] - __uint_as_float(uA1 & 0xFFFF0000u));
                pl[1] = pkbf(sA[2] - __uint_as_float(uA2 & 0xFFFF0000u),
                             sA[3] - __uint_as_float(uA3 & 0xFFFF0000u));
                pl[2] = pkbf(sB[0] - __uint_as_float(uB0 & 0xFFFF0000u),
                             sB[1] - __uint_as_float(uB1 & 0xFFFF0000u));
                pl[3] = pkbf(sB[2] - __uint_as_float(uB2 & 0xFFFF0000u),
                             sB[3] - __uint_as_float(uB3 & 0xFFFF0000u));
            }
#pragma unroll
            for (int nv = 0; nv < 4; nv++) {
                uint32_t vh[4], vl[4];
                const uint32_t vo = (uint32_t)((kf * 16 + (lane & 15)) * ASTRB +
                                               (lane >> 4) * 16 + nv * 32);
                ldm4t(vh, sstage + VH_O + vo);
                mma_bf16(O[2 * nv],     ph, vh[0], vh[1]);
                mma_bf16(O[2 * nv + 1], ph, vh[2], vh[3]);
                ldm4t(vl, sstage + VL_O + vo);
                mma_bf16(O[2 * nv],     ph, vl[0], vl[1]);
                mma_bf16(O[2 * nv + 1], ph, vl[2], vl[3]);
                mma_bf16(O[2 * nv],     pl, vh[0], vh[1]);
                mma_bf16(O[2 * nv + 1], pl, vh[2], vh[3]);
            }
        }
        __syncthreads();   // all warps done with stage w4&1 before iter w4+1 overwrites it
    }

    l0 += __shfl_xor_sync(0xFFFFFFFF, l0, 1);
    l0 += __shfl_xor_sync(0xFFFFFFFF, l0, 2);
    l1 += __shfl_xor_sync(0xFFFFFFFF, l1, 1);
    l1 += __shfl_xor_sync(0xFFFFFFFF, l1, 2);
    const float inv0 = 1.f / l0, inv1 = 1.f / l1;
    const int gq = lane >> 2, tig = lane & 3;
    const int qs0 = token_of(t, w * 16 + gq);
    const int qs1 = token_of(t, w * 16 + gq + 8);
    const size_t r0 = base + (size_t)qs0 * NHD;
    const size_t r1 = base + (size_t)qs1 * NHD;
#pragma unroll
    for (int nf = 0; nf < 8; nf++) {
        const int col = nf * 8 + tig * 2;
        const float x0 = O[nf][0] * inv0, x1 = O[nf][1] * inv0;
        const float x2 = O[nf][2] * inv1, x3 = O[nf][3] * inv1;
        const __nv_bfloat16 h0 = __float2bfloat16(x0), h1 = __float2bfloat16(x1);
        const __nv_bfloat16 h2 = __float2bfloat16(x2), h3 = __float2bfloat16(x3);
        *(__nv_bfloat162*)&Ohi[r0 + col] = __nv_bfloat162(h0, h1);
        *(__nv_bfloat162*)&Ohi[r1 + col] = __nv_bfloat162(h2, h3);
        *(__nv_bfloat162*)&Olo[r0 + col] = __nv_bfloat162(
            __float2bfloat16(x0 - __bfloat162float(h0)),
            __float2bfloat16(x1 - __bfloat162float(h1)));
        *(__nv_bfloat162*)&Olo[r1 + col] = __nv_bfloat162(
            __float2bfloat16(x2 - __bfloat162float(h2)),
            __float2bfloat16(x3 - __bfloat162float(h3)));
    }
}

// ---------------------------------------------------------------------------
// Launch
// ---------------------------------------------------------------------------
extern "C" void kernel_launch(void* const* d_in, const int* in_sizes, int n_in,
                              void* d_out, int out_size)
{
    const float* hs = (const float*)d_in[0];
    const float* Wq = (const float*)d_in[1];
    const float* Wk = (const float*)d_in[2];
    const float* Wv = (const float*)d_in[3];
    const float* Wo = (const float*)d_in[4];
    float* out = (float*)d_out;

    __nv_bfloat16 *hshi, *hslo, *wthi, *wtlo;
    __nv_bfloat16 *qhi, *qlo, *khi, *klo, *vhi, *vlo, *atthi, *attlo;
    cudaGetSymbolAddress((void**)&hshi, g_hshi);
    cudaGetSymbolAddress((void**)&hslo, g_hslo);
    cudaGetSymbolAddress((void**)&wthi, g_wthi);
    cudaGetSymbolAddress((void**)&wtlo, g_wtlo);
    cudaGetSymbolAddress((void**)&qhi, g_qhi);
    cudaGetSymbolAddress((void**)&qlo, g_qlo);
    cudaGetSymbolAddress((void**)&khi, g_khi);
    cudaGetSymbolAddress((void**)&klo, g_klo);
    cudaGetSymbolAddress((void**)&vhi, g_vhi);
    cudaGetSymbolAddress((void**)&vlo, g_vlo);
    cudaGetSymbolAddress((void**)&atthi, g_atthi);
    cudaGetSymbolAddress((void**)&attlo, g_attlo);

    cudaFuncSetAttribute(qkv_mma_kernel, cudaFuncAttributeMaxDynamicSharedMemorySize, GEMM_SMEM);
    cudaFuncSetAttribute(out_mma_kernel, cudaFuncAttributeMaxDynamicSharedMemorySize, GEMM_SMEM);
    cudaFuncSetAttribute(attn_mma_kernel, cudaFuncAttributeMaxDynamicSharedMemorySize, ATT_SMEM);

    const int n4 = (M_ROWS * HID) / 4;
    split_kernel<<<(n4 + 255) / 256, 256>>>(hs, hshi, hslo, n4);
    wsplit_kernel<<<dim3(NHD / 32, HID / 32, 4), dim3(32, 8)>>>(Wq, Wk, Wv, Wo, wthi, wtlo);

    qkv_mma_kernel<<<dim3(NHD / 128, M_ROWS / 128, 3), 128, GEMM_SMEM>>>(
        hshi, hslo, wthi, wtlo, qhi, qlo, khi, klo, vhi, vlo);

    attn_mma_kernel<<<dim3(NT, NH, B_SZ), 256, ATT_SMEM>>>(
        qhi, qlo, khi, klo, vhi, vlo, atthi, attlo);

    const size_t WSZ = (size_t)HID * NHD;
    out_mma_kernel<<<dim3(HID / 128, M_ROWS / 128), 128, GEMM_SMEM>>>(
        atthi, attlo, wthi + 3 * WSZ, wtlo + 3 * WSZ, out);
}

// round 11
// speedup vs baseline: 1.5192x; 1.5192x over previous
#include <cuda_runtime.h>
#include <cuda_bf16.h>
#include <cstdint>
#include <cstddef>

// ---------------------------------------------------------------------------
// Problem constants
// ---------------------------------------------------------------------------
#define B_SZ   2
#define S_SZ   4096
#define HID    2048
#define NH     32
#define HD     64
#define NHD    2048
#define M_ROWS (B_SZ * S_SZ)       // 8192
#define NT     32
#define NKV    4
#define SCALE_F 0.125f
#define KDIM   2048

// ---------------------------------------------------------------------------
// PTX helpers (plain sm_80+ features only)
// ---------------------------------------------------------------------------
__device__ __forceinline__ uint32_t smem_u32(const void* p) {
    uint32_t a;
    asm("{ .reg .u64 t; cvta.to.shared.u64 t, %1; cvt.u32.u64 %0, t; }" : "=r"(a) : "l"(p));
    return a;
}
#define CP_ASYNC16(dst, src) \
    asm volatile("cp.async.cg.shared.global [%0], [%1], 16;" :: "r"(dst), "l"(src) : "memory")
#define CP_COMMIT()  asm volatile("cp.async.commit_group;" ::: "memory")
#define CP_WAIT(n)   asm volatile("cp.async.wait_group %0;" :: "n"(n) : "memory")

__device__ __forceinline__ void ldm4(uint32_t* r, uint32_t addr) {
    asm volatile("ldmatrix.sync.aligned.m8n8.x4.shared.b16 {%0,%1,%2,%3}, [%4];"
        : "=r"(r[0]), "=r"(r[1]), "=r"(r[2]), "=r"(r[3]) : "r"(addr));
}
__device__ __forceinline__ void ldm4t(uint32_t* r, uint32_t addr) {
    asm volatile("ldmatrix.sync.aligned.m8n8.x4.trans.shared.b16 {%0,%1,%2,%3}, [%4];"
        : "=r"(r[0]), "=r"(r[1]), "=r"(r[2]), "=r"(r[3]) : "r"(addr));
}
__device__ __forceinline__ void mma_bf16(float* d, const uint32_t* a, uint32_t b0, uint32_t b1) {
    asm volatile("mma.sync.aligned.m16n8k16.row.col.f32.bf16.bf16.f32 "
        "{%0,%1,%2,%3}, {%4,%5,%6,%7}, {%8,%9}, {%0,%1,%2,%3};"
        : "+f"(d[0]), "+f"(d[1]), "+f"(d[2]), "+f"(d[3])
        : "r"(a[0]), "r"(a[1]), "r"(a[2]), "r"(a[3]), "r"(b0), "r"(b1));
}
__device__ __forceinline__ uint32_t pkbf(float a, float b) {
    __nv_bfloat162 t(__float2bfloat16(a), __float2bfloat16(b));
    return *(uint32_t*)&t;
}

// ---------------------------------------------------------------------------
// Scratch (device globals)
// ---------------------------------------------------------------------------
__device__ __nv_bfloat16 g_hshi[M_ROWS * HID];
__device__ __nv_bfloat16 g_hslo[M_ROWS * HID];
__device__ __nv_bfloat16 g_wthi[4 * HID * NHD];
__device__ __nv_bfloat16 g_wtlo[4 * HID * NHD];
__device__ __nv_bfloat16 g_qhi[M_ROWS * NHD];
__device__ __nv_bfloat16 g_qlo[M_ROWS * NHD];
__device__ __nv_bfloat16 g_khi[M_ROWS * NHD];
__device__ __nv_bfloat16 g_klo[M_ROWS * NHD];
__device__ __nv_bfloat16 g_vhi[M_ROWS * NHD];
__device__ __nv_bfloat16 g_vlo[M_ROWS * NHD];
__device__ __nv_bfloat16 g_atthi[M_ROWS * NHD];
__device__ __nv_bfloat16 g_attlo[M_ROWS * NHD];

// ---------------------------------------------------------------------------
// Pre-pass 1: elementwise fp32 -> (hi, lo) bf16 split
// ---------------------------------------------------------------------------
__global__ void split_kernel(const float* __restrict__ x,
                             __nv_bfloat16* __restrict__ hi,
                             __nv_bfloat16* __restrict__ lo, int n4)
{
    int i = blockIdx.x * blockDim.x + threadIdx.x;
    if (i >= n4) return;
    const float4 v = ((const float4*)x)[i];
    __nv_bfloat16 h0 = __float2bfloat16(v.x), h1 = __float2bfloat16(v.y);
    __nv_bfloat16 h2 = __float2bfloat16(v.z), h3 = __float2bfloat16(v.w);
    __nv_bfloat16 l0 = __float2bfloat16(v.x - __bfloat162float(h0));
    __nv_bfloat16 l1 = __float2bfloat16(v.y - __bfloat162float(h1));
    __nv_bfloat16 l2 = __float2bfloat16(v.z - __bfloat162float(h2));
    __nv_bfloat16 l3 = __float2bfloat16(v.w - __bfloat162float(h3));
    ((__nv_bfloat162*)hi)[i * 2]     = __nv_bfloat162(h0, h1);
    ((__nv_bfloat162*)hi)[i * 2 + 1] = __nv_bfloat162(h2, h3);
    ((__nv_bfloat162*)lo)[i * 2]     = __nv_bfloat162(l0, l1);
    ((__nv_bfloat162*)lo)[i * 2 + 1] = __nv_bfloat162(l2, l3);
}

// ---------------------------------------------------------------------------
// Pre-pass 2: W[K,N] -> Wt[N,K] with bf16 hi/lo split
// ---------------------------------------------------------------------------
__global__ void wsplit_kernel(const float* __restrict__ W0, const float* __restrict__ W1,
                              const float* __restrict__ W2, const float* __restrict__ W3,
                              __nv_bfloat16* __restrict__ hi, __nv_bfloat16* __restrict__ lo)
{
    const int z = blockIdx.z;
    const float* W = (z == 0) ? W0 : (z == 1) ? W1 : (z == 2) ? W2 : W3;
    __shared__ float t[32][33];
    const int n0 = blockIdx.x * 32, k0 = blockIdx.y * 32;
    const int tx = threadIdx.x, ty = threadIdx.y;
#pragma unroll
    for (int i = 0; i < 4; i++)
        t[ty + 8 * i][tx] = W[(size_t)(k0 + ty + 8 * i) * NHD + n0 + tx];
    __syncthreads();
    const size_t zo = (size_t)z * HID * NHD;
#pragma unroll
    for (int i = 0; i < 4; i++) {
        const float x = t[tx][ty + 8 * i];
        const __nv_bfloat16 h = __float2bfloat16(x);
        const __nv_bfloat16 l = __float2bfloat16(x - __bfloat162float(h));
        const size_t o = zo + (size_t)(n0 + ty + 8 * i) * KDIM + k0 + tx;
        hi[o] = h;
        lo[o] = l;
    }
}

// ---------------------------------------------------------------------------
// Split-bf16 HMMA GEMM (exact R7 best config): CTA 128x128, 4 warps (64x64),
// BK=32, 2-stage cp.async double buffer, 80KB smem -> 2 CTAs/SM.
// SPLIT epilogue multiplies by cscale (0.125 for Q, exact power of 2).
// ---------------------------------------------------------------------------
#define BK        32
#define NITER     (KDIM / BK)           // 64
#define STR_B     80
#define MAT_B     (128 * STR_B)         // 10240
#define OFF_AH    0
#define OFF_AL    MAT_B
#define OFF_BH    (2 * MAT_B)
#define OFF_BL    (3 * MAT_B)
#define STAGE_B   (4 * MAT_B)           // 40960
#define GEMM_SMEM (2 * STAGE_B)         // 81920

struct GemmPtrs {
    const __nv_bfloat16 *Ahi, *Alo, *Bhi, *Blo;
    float* C;
    __nv_bfloat16 *Chi, *Clo;
    float cscale;
};

__device__ __forceinline__ void gemm_copy_stage(
    uint32_t sdst, const GemmPtrs& g, int m0, int n0, int kb, int tid)
{
#pragma unroll
    for (int i = 0; i < 16; i++) {
        const int idx = tid + i * 128;
        const int mat = idx >> 9, rem = idx & 511;
        const int row = rem >> 2, c = rem & 3;
        const __nv_bfloat16* sp;
        if (mat == 0)      sp = g.Ahi + (size_t)(m0 + row) * KDIM + kb + c * 8;
        else if (mat == 1) sp = g.Alo + (size_t)(m0 + row) * KDIM + kb + c * 8;
        else if (mat == 2) sp = g.Bhi + (size_t)(n0 + row) * KDIM + kb + c * 8;
        else               sp = g.Blo + (size_t)(n0 + row) * KDIM + kb + c * 8;
        CP_ASYNC16(sdst + mat * MAT_B + row * STR_B + c * 16, sp);
    }
    CP_COMMIT();
}

template <bool SPLIT>
__device__ __forceinline__ void gemm_body_mma(const GemmPtrs& g)
{
    extern __shared__ __align__(128) char smem[];
    const uint32_t sbase = smem_u32(smem);
    const int tid = threadIdx.x, wid = tid >> 5, lane = tid & 31;
    const int m0 = blockIdx.y * 128, n0 = blockIdx.x * 128;
    const int wm = wid & 1, wn = wid >> 1;

    float acc[4][8][4];
#pragma unroll
    for (int a = 0; a < 4; a++)
#pragma unroll
        for (int b = 0; b < 8; b++)
#pragma unroll
            for (int c = 0; c < 4; c++) acc[a][b][c] = 0.f;

    const uint32_t lofs = (uint32_t)((lane & 15) * STR_B + (lane >> 4) * 16);

    gemm_copy_stage(sbase, g, m0, n0, 0, tid);

    for (int t = 0; t < NITER; ++t) {
        if (t + 1 < NITER) {
            gemm_copy_stage(sbase + ((t + 1) & 1) * STAGE_B, g, m0, n0, (t + 1) * BK, tid);
            CP_WAIT(1);
        } else {
            CP_WAIT(0);
        }
        __syncthreads();

        const uint32_t s0 = sbase + (t & 1) * STAGE_B;
#pragma unroll
        for (int ks = 0; ks < 2; ++ks) {
            const uint32_t aoff = s0 + OFF_AH + (uint32_t)(wm * 64 * STR_B + ks * 32) + lofs;
            uint32_t Ah[16], Al[16];
#pragma unroll
            for (int mf = 0; mf < 4; mf++) {
                ldm4(Ah + mf * 4, aoff + mf * 16 * STR_B);
                ldm4(Al + mf * 4, aoff + (OFF_AL - OFF_AH) + mf * 16 * STR_B);
            }
#pragma unroll
            for (int half = 0; half < 2; half++) {
                const uint32_t boff = s0 + OFF_BH +
                    (uint32_t)((wn * 64 + half * 32) * STR_B + ks * 32) + lofs;
                uint32_t Bh[8], Bl[8];
                ldm4(Bh + 0, boff);
                ldm4(Bh + 4, boff + 16 * STR_B);
                ldm4(Bl + 0, boff + (OFF_BL - OFF_BH));
                ldm4(Bl + 4, boff + (OFF_BL - OFF_BH) + 16 * STR_B);
#pragma unroll
                for (int mf = 0; mf < 4; mf++)
#pragma unroll
                    for (int nl = 0; nl < 4; nl++) {
                        float* d = acc[mf][half * 4 + nl];
                        const uint32_t b0i = (nl >> 1) * 4 + (nl & 1);
                        mma_bf16(d, Ah + mf * 4, Bh[b0i], Bh[b0i + 2]);
                        mma_bf16(d, Ah + mf * 4, Bl[b0i], Bl[b0i + 2]);
                        mma_bf16(d, Al + mf * 4, Bh[b0i], Bh[b0i + 2]);
                    }
            }
        }
        __syncthreads();
    }

    const int gq = lane >> 2, tig = lane & 3;
#pragma unroll
    for (int mf = 0; mf < 4; mf++) {
        const int row = m0 + wm * 64 + mf * 16 + gq;
#pragma unroll
        for (int nf = 0; nf < 8; nf++) {
            const int col = n0 + wn * 64 + nf * 8 + tig * 2;
            if (SPLIT) {
#pragma unroll
                for (int half = 0; half < 2; half++) {
                    const size_t off = (size_t)(row + half * 8) * 2048 + col;
                    const float x0 = acc[mf][nf][half * 2] * g.cscale;
                    const float x1 = acc[mf][nf][half * 2 + 1] * g.cscale;
                    const __nv_bfloat16 h0 = __float2bfloat16(x0), h1 = __float2bfloat16(x1);
                    const __nv_bfloat16 l0 = __float2bfloat16(x0 - __bfloat162float(h0));
                    const __nv_bfloat16 l1 = __float2bfloat16(x1 - __bfloat162float(h1));
                    *(__nv_bfloat162*)&g.Chi[off] = __nv_bfloat162(h0, h1);
                    *(__nv_bfloat162*)&g.Clo[off] = __nv_bfloat162(l0, l1);
                }
            } else {
                *(float2*)&g.C[(size_t)row * 2048 + col] =
                    make_float2(acc[mf][nf][0], acc[mf][nf][1]);
                *(float2*)&g.C[(size_t)(row + 8) * 2048 + col] =
                    make_float2(acc[mf][nf][2], acc[mf][nf][3]);
            }
        }
    }
}

__global__ __launch_bounds__(128, 2) void qkv_mma_kernel(
    const __nv_bfloat16* __restrict__ Ahi, const __nv_bfloat16* __restrict__ Alo,
    const __nv_bfloat16* __restrict__ Whi, const __nv_bfloat16* __restrict__ Wlo,
    __nv_bfloat16* __restrict__ Qh, __nv_bfloat16* __restrict__ Ql,
    __nv_bfloat16* __restrict__ Kh, __nv_bfloat16* __restrict__ Kl,
    __nv_bfloat16* __restrict__ Vh, __nv_bfloat16* __restrict__ Vl)
{
    const size_t WSZ = (size_t)HID * NHD;
    const int z = blockIdx.z;
    GemmPtrs g;
    g.Ahi = Ahi; g.Alo = Alo;
    g.Bhi = Whi + (size_t)z * WSZ; g.Blo = Wlo + (size_t)z * WSZ;
    g.C = nullptr;
    g.Chi = (z == 0) ? Qh : (z == 1) ? Kh : Vh;
    g.Clo = (z == 0) ? Ql : (z == 1) ? Kl : Vl;
    g.cscale = (z == 0) ? SCALE_F : 1.0f;   // fold softmax scale into Q (exact: 2^-3)
    gemm_body_mma<true>(g);
}

__global__ __launch_bounds__(128, 2) void out_mma_kernel(
    const __nv_bfloat16* __restrict__ Ahi, const __nv_bfloat16* __restrict__ Alo,
    const __nv_bfloat16* __restrict__ Whi, const __nv_bfloat16* __restrict__ Wlo,
    float* __restrict__ C)
{
    GemmPtrs g;
    g.Ahi = Ahi; g.Alo = Alo; g.Bhi = Whi; g.Blo = Wlo;
    g.C = C; g.Chi = nullptr; g.Clo = nullptr; g.cscale = 1.0f;
    gemm_body_mma<false>(g);
}

// ---------------------------------------------------------------------------
// Tensor-core flash attention (split-bf16, 3 products), single-buffered
// (R5/R7 proven config). Scale pre-folded into Q. P hi/lo via truncation.
// ---------------------------------------------------------------------------
#define ASTRB   144
#define AQH     0
#define AQL     18432
#define AKH     36864
#define AKL     55296
#define AVH     73728
#define AVL     92160
#define ATT_SMEM 110592

__device__ __forceinline__ int token_of(int tile, int jj)
{
    return ((tile >> 2) << 9) + ((jj >> 4) << 6) + ((tile & 3) << 4) + (jj & 15);
}

__global__ __launch_bounds__(256, 1) void attn_mma_kernel(
    const __nv_bfloat16* __restrict__ Qhi, const __nv_bfloat16* __restrict__ Qlo,
    const __nv_bfloat16* __restrict__ Khi, const __nv_bfloat16* __restrict__ Klo,
    const __nv_bfloat16* __restrict__ Vhi, const __nv_bfloat16* __restrict__ Vlo,
    __nv_bfloat16* __restrict__ Ohi, __nv_bfloat16* __restrict__ Olo)
{
    extern __shared__ __align__(128) char smem[];
    const uint32_t sbase = smem_u32(smem);
    const int t = blockIdx.x, h = blockIdx.y, b = blockIdx.z;
    const int tid = threadIdx.x, w = tid >> 5, lane = tid & 31;
    const size_t base = (size_t)b * S_SZ * NHD + (size_t)h * HD;

    const int tr = t >> 2, tc = t & 3;
    const int cr = min(max(tr, 1), 7);
    const int cc = min(max(tc, 1), 3);
    int kts[NKV];
    kts[0] = (cr - 1) * 4 + (cc - 1);
    kts[1] = (cr - 1) * 4 + cc;
    kts[2] = cr * 4 + (cc - 1);
    kts[3] = cr * 4 + cc;

    for (int i = tid; i < 2048; i += 256) {
        const int mat = i >> 10, rem = i & 1023;
        const int row = rem >> 3, c = rem & 7;
        const int qs = token_of(t, row);
        const __nv_bfloat16* src = (mat ? Qlo : Qhi) + base + (size_t)qs * NHD + c * 8;
        CP_ASYNC16(sbase + (mat ? AQL : AQH) + row * ASTRB + c * 16, src);
    }
    CP_COMMIT();
    CP_WAIT(0);
    __syncthreads();

    uint32_t qh[4][4], ql[4][4];
    const uint32_t qoff = (uint32_t)((w * 16 + (lane & 15)) * ASTRB + (lane >> 4) * 16);
#pragma unroll
    for (int kf = 0; kf < 4; kf++) {
        ldm4(qh[kf], sbase + AQH + qoff + kf * 32);
        ldm4(ql[kf], sbase + AQL + qoff + kf * 32);
    }

    float O[8][4];
#pragma unroll
    for (int nf = 0; nf < 8; nf++)
#pragma unroll
        for (int c = 0; c < 4; c++) O[nf][c] = 0.f;
    float m0 = -1e30f, m1 = -1e30f, l0 = 0.f, l1 = 0.f;

    for (int w4 = 0; w4 < NKV; ++w4) {
        const int kt = kts[w4];
        __syncthreads();
        for (int i = tid; i < 4096; i += 256) {
            const int mat = i >> 10, rem = i & 1023;
            const int row = rem >> 3, c = rem & 7;
            const int ks = token_of(kt, row);
            const size_t off = base + (size_t)ks * NHD + c * 8;
            const __nv_bfloat16* src =
                (mat == 0) ? Khi + off : (mat == 1) ? Klo + off :
                (mat == 2) ? Vhi + off : Vlo + off;
            const uint32_t doff = (mat == 0) ? AKH : (mat == 1) ? AKL :
                                  (mat == 2) ? AVH : AVL;
            CP_ASYNC16(sbase + doff + row * ASTRB + c * 16, src);
        }
        CP_COMMIT();
        CP_WAIT(0);
        __syncthreads();

        // ---- S = Q @ K^T (scale already folded into Q) ----
        float S[16][4];
#pragma unroll
        for (int nf = 0; nf < 16; nf++)
#pragma unroll
            for (int c = 0; c < 4; c++) S[nf][c] = 0.f;

#pragma unroll
        for (int kf = 0; kf < 4; kf++) {
#pragma unroll
            for (int g = 0; g < 8; g++) {
                uint32_t kh[4], kl[4];
                const uint32_t ko = (uint32_t)((g * 16 + (lane & 15)) * ASTRB +
                                               (lane >> 4) * 16 + kf * 32);
                ldm4(kh, sbase + AKH + ko);
                mma_bf16(S[2 * g],     qh[kf], kh[0], kh[2]);
                mma_bf16(S[2 * g + 1], qh[kf], kh[1], kh[3]);
                ldm4(kl, sbase + AKL + ko);
                mma_bf16(S[2 * g],     qh[kf], kl[0], kl[2]);
                mma_bf16(S[2 * g + 1], qh[kf], kl[1], kl[3]);
                mma_bf16(S[2 * g],     ql[kf], kh[0], kh[2]);
                mma_bf16(S[2 * g + 1], ql[kf], kh[1], kh[3]);
            }
        }

        // ---- online softmax ----
        float tmax0 = -1e30f, tmax1 = -1e30f;
#pragma unroll
        for (int nf = 0; nf < 16; nf++) {
            tmax0 = fmaxf(tmax0, fmaxf(S[nf][0], S[nf][1]));
            tmax1 = fmaxf(tmax1, fmaxf(S[nf][2], S[nf][3]));
        }
        tmax0 = fmaxf(tmax0, __shfl_xor_sync(0xFFFFFFFF, tmax0, 1));
        tmax0 = fmaxf(tmax0, __shfl_xor_sync(0xFFFFFFFF, tmax0, 2));
        tmax1 = fmaxf(tmax1, __shfl_xor_sync(0xFFFFFFFF, tmax1, 1));
        tmax1 = fmaxf(tmax1, __shfl_xor_sync(0xFFFFFFFF, tmax1, 2));

        const float mn0 = fmaxf(m0, tmax0), mn1 = fmaxf(m1, tmax1);
        const float a0 = __expf(m0 - mn0), a1 = __expf(m1 - mn1);
        m0 = mn0; m1 = mn1;
        l0 *= a0; l1 *= a1;
#pragma unroll
        for (int nf = 0; nf < 8; nf++) {
            O[nf][0] *= a0; O[nf][1] *= a0;
            O[nf][2] *= a1; O[nf][3] *= a1;
        }
        float ls0 = 0.f, ls1 = 0.f;
#pragma unroll
        for (int nf = 0; nf < 16; nf++) {
            S[nf][0] = __expf(S[nf][0] - m0); ls0 += S[nf][0];
            S[nf][1] = __expf(S[nf][1] - m0); ls0 += S[nf][1];
            S[nf][2] = __expf(S[nf][2] - m1); ls1 += S[nf][2];
            S[nf][3] = __expf(S[nf][3] - m1); ls1 += S[nf][3];
        }
        l0 += ls0; l1 += ls1;

        // ---- O += P @ V; P hi via truncation mask, residual exact ----
#pragma unroll
        for (int kf = 0; kf < 8; kf++) {
            uint32_t ph[4], pl[4];
            {
                const float* sA = S[2 * kf];
                const float* sB = S[2 * kf + 1];
                const uint32_t uA0 = __float_as_uint(sA[0]), uA1 = __float_as_uint(sA[1]);
                const uint32_t uA2 = __float_as_uint(sA[2]), uA3 = __float_as_uint(sA[3]);
                const uint32_t uB0 = __float_as_uint(sB[0]), uB1 = __float_as_uint(sB[1]);
                const uint32_t uB2 = __float_as_uint(sB[2]), uB3 = __float_as_uint(sB[3]);
                ph[0] = __byte_perm(uA0, uA1, 0x7632);
                ph[1] = __byte_perm(uA2, uA3, 0x7632);
                ph[2] = __byte_perm(uB0, uB1, 0x7632);
                ph[3] = __byte_perm(uB2, uB3, 0x7632);
                pl[0] = pkbf(sA[0] - __uint_as_float(uA0 & 0xFFFF0000u),
                             sA[1] - __uint_as_float(uA1 & 0xFFFF0000u));
                pl[1] = pkbf(sA[2] - __uint_as_float(uA2 & 0xFFFF0000u),
                             sA[3] - __uint_as_float(uA3 & 0xFFFF0000u));
                pl[2] = pkbf(sB[0] - __uint_as_float(uB0 & 0xFFFF0000u),
                             sB[1] - __uint_as_float(uB1 & 0xFFFF0000u));
                pl[3] = pkbf(sB[2] - __uint_as_float(uB2 & 0xFFFF0000u),
                             sB[3] - __uint_as_float(uB3 & 0xFFFF0000u));
            }
#pragma unroll
            for (int nv = 0; nv < 4; nv++) {
                uint32_t vh[4], vl[4];
                const uint32_t vo = (uint32_t)((kf * 16 + (lane & 15)) * ASTRB +
                                               (lane >> 4) * 16 + nv * 32);
                ldm4t(vh, sbase + AVH + vo);
                mma_bf16(O[2 * nv],     ph, vh[0], vh[1]);
                mma_bf16(O[2 * nv + 1], ph, vh[2], vh[3]);
                ldm4t(vl, sbase + AVL + vo);
                mma_bf16(O[2 * nv],     ph, vl[0], vl[1]);
                mma_bf16(O[2 * nv + 1], ph, vl[2], vl[3]);
                mma_bf16(O[2 * nv],     pl, vh[0], vh[1]);
                mma_bf16(O[2 * nv + 1], pl, vh[2], vh[3]);
            }
        }
    }

    l0 += __shfl_xor_sync(0xFFFFFFFF, l0, 1);
    l0 += __shfl_xor_sync(0xFFFFFFFF, l0, 2);
    l1 += __shfl_xor_sync(0xFFFFFFFF, l1, 1);
    l1 += __shfl_xor_sync(0xFFFFFFFF, l1, 2);
    const float inv0 = 1.f / l0, inv1 = 1.f / l1;
    const int gq = lane >> 2, tig = lane & 3;
    const int qs0 = token_of(t, w * 16 + gq);
    const int qs1 = token_of(t, w * 16 + gq + 8);
    const size_t r0 = base + (size_t)qs0 * NHD;
    const size_t r1 = base + (size_t)qs1 * NHD;
#pragma unroll
    for (int nf = 0; nf < 8; nf++) {
        const int col = nf * 8 + tig * 2;
        const float x0 = O[nf][0] * inv0, x1 = O[nf][1] * inv0;
        const float x2 = O[nf][2] * inv1, x3 = O[nf][3] * inv1;
        const __nv_bfloat16 h0 = __float2bfloat16(x0), h1 = __float2bfloat16(x1);
        const __nv_bfloat16 h2 = __float2bfloat16(x2), h3 = __float2bfloat16(x3);
        *(__nv_bfloat162*)&Ohi[r0 + col] = __nv_bfloat162(h0, h1);
        *(__nv_bfloat162*)&Ohi[r1 + col] = __nv_bfloat162(h2, h3);
        *(__nv_bfloat162*)&Olo[r0 + col] = __nv_bfloat162(
            __float2bfloat16(x0 - __bfloat162float(h0)),
            __float2bfloat16(x1 - __bfloat162float(h1)));
        *(__nv_bfloat162*)&Olo[r1 + col] = __nv_bfloat162(
            __float2bfloat16(x2 - __bfloat162float(h2)),
            __float2bfloat16(x3 - __bfloat162float(h3)));
    }
}

// ---------------------------------------------------------------------------
// Launch
// ---------------------------------------------------------------------------
extern "C" void kernel_launch(void* const* d_in, const int* in_sizes, int n_in,
                              void* d_out, int out_size)
{
    const float* hs = (const float*)d_in[0];
    const float* Wq = (const float*)d_in[1];
    const float* Wk = (const float*)d_in[2];
    const float* Wv = (const float*)d_in[3];
    const float* Wo = (const float*)d_in[4];
    float* out = (float*)d_out;

    __nv_bfloat16 *hshi, *hslo, *wthi, *wtlo;
    __nv_bfloat16 *qhi, *qlo, *khi, *klo, *vhi, *vlo, *atthi, *attlo;
    cudaGetSymbolAddress((void**)&hshi, g_hshi);
    cudaGetSymbolAddress((void**)&hslo, g_hslo);
    cudaGetSymbolAddress((void**)&wthi, g_wthi);
    cudaGetSymbolAddress((void**)&wtlo, g_wtlo);
    cudaGetSymbolAddress((void**)&qhi, g_qhi);
    cudaGetSymbolAddress((void**)&qlo, g_qlo);
    cudaGetSymbolAddress((void**)&khi, g_khi);
    cudaGetSymbolAddress((void**)&klo, g_klo);
    cudaGetSymbolAddress((void**)&vhi, g_vhi);
    cudaGetSymbolAddress((void**)&vlo, g_vlo);
    cudaGetSymbolAddress((void**)&atthi, g_atthi);
    cudaGetSymbolAddress((void**)&attlo, g_attlo);

    cudaFuncSetAttribute(qkv_mma_kernel, cudaFuncAttributeMaxDynamicSharedMemorySize, GEMM_SMEM);
    cudaFuncSetAttribute(out_mma_kernel, cudaFuncAttributeMaxDynamicSharedMemorySize, GEMM_SMEM);
    cudaFuncSetAttribute(attn_mma_kernel, cudaFuncAttributeMaxDynamicSharedMemorySize, ATT_SMEM);

    const int n4 = (M_ROWS * HID) / 4;
    split_kernel<<<(n4 + 255) / 256, 256>>>(hs, hshi, hslo, n4);
    wsplit_kernel<<<dim3(NHD / 32, HID / 32, 4), dim3(32, 8)>>>(Wq, Wk, Wv, Wo, wthi, wtlo);

    qkv_mma_kernel<<<dim3(NHD / 128, M_ROWS / 128, 3), 128, GEMM_SMEM>>>(
        hshi, hslo, wthi, wtlo, qhi, qlo, khi, klo, vhi, vlo);

    attn_mma_kernel<<<dim3(NT, NH, B_SZ), 256, ATT_SMEM>>>(
        qhi, qlo, khi, klo, vhi, vlo, atthi, attlo);

    const size_t WSZ = (size_t)HID * NHD;
    out_mma_kernel<<<dim3(HID / 128, M_ROWS / 128), 128, GEMM_SMEM>>>(
        atthi, attlo, wthi + 3 * WSZ, wtlo + 3 * WSZ, out);
}

// round 12
// speedup vs baseline: 2.1670x; 1.4264x over previous
#include <cuda_runtime.h>
#include <cuda_bf16.h>
#include <cstdint>
#include <cstddef>

// ---------------------------------------------------------------------------
// Problem constants
// ---------------------------------------------------------------------------
#define B_SZ   2
#define S_SZ   4096
#define HID    2048
#define NH     32
#define HD     64
#define NHD    2048
#define M_ROWS (B_SZ * S_SZ)       // 8192
#define NT     32
#define NKV    4
#define SCALE_F 0.125f
#define KDIM   2048

// ---------------------------------------------------------------------------
// PTX helpers (plain sm_80+ features only)
// ---------------------------------------------------------------------------
__device__ __forceinline__ uint32_t smem_u32(const void* p) {
    uint32_t a;
    asm("{ .reg .u64 t; cvta.to.shared.u64 t, %1; cvt.u32.u64 %0, t; }" : "=r"(a) : "l"(p));
    return a;
}
#define CP_ASYNC16(dst, src) \
    asm volatile("cp.async.cg.shared.global [%0], [%1], 16;" :: "r"(dst), "l"(src) : "memory")
#define CP_COMMIT()  asm volatile("cp.async.commit_group;" ::: "memory")
#define CP_WAIT(n)   asm volatile("cp.async.wait_group %0;" :: "n"(n) : "memory")

__device__ __forceinline__ void ldm4(uint32_t* r, uint32_t addr) {
    asm volatile("ldmatrix.sync.aligned.m8n8.x4.shared.b16 {%0,%1,%2,%3}, [%4];"
        : "=r"(r[0]), "=r"(r[1]), "=r"(r[2]), "=r"(r[3]) : "r"(addr));
}
__device__ __forceinline__ void ldm4t(uint32_t* r, uint32_t addr) {
    asm volatile("ldmatrix.sync.aligned.m8n8.x4.trans.shared.b16 {%0,%1,%2,%3}, [%4];"
        : "=r"(r[0]), "=r"(r[1]), "=r"(r[2]), "=r"(r[3]) : "r"(addr));
}
__device__ __forceinline__ void mma_bf16(float* d, const uint32_t* a, uint32_t b0, uint32_t b1) {
    asm volatile("mma.sync.aligned.m16n8k16.row.col.f32.bf16.bf16.f32 "
        "{%0,%1,%2,%3}, {%4,%5,%6,%7}, {%8,%9}, {%0,%1,%2,%3};"
        : "+f"(d[0]), "+f"(d[1]), "+f"(d[2]), "+f"(d[3])
        : "r"(a[0]), "r"(a[1]), "r"(a[2]), "r"(a[3]), "r"(b0), "r"(b1));
}
__device__ __forceinline__ void mma_tf32(float* d, const uint32_t* a, uint32_t b0, uint32_t b1) {
    asm volatile("mma.sync.aligned.m16n8k8.row.col.f32.tf32.tf32.f32 "
        "{%0,%1,%2,%3}, {%4,%5,%6,%7}, {%8,%9}, {%0,%1,%2,%3};"
        : "+f"(d[0]), "+f"(d[1]), "+f"(d[2]), "+f"(d[3])
        : "r"(a[0]), "r"(a[1]), "r"(a[2]), "r"(a[3]), "r"(b0), "r"(b1));
}
__device__ __forceinline__ uint32_t pkbf(float a, float b) {
    __nv_bfloat162 t(__float2bfloat16(a), __float2bfloat16(b));
    return *(uint32_t*)&t;
}
__device__ __forceinline__ float rna_tf32(float x) {
    uint32_t r;
    asm("cvt.rna.tf32.f32 %0, %1;" : "=r"(r) : "f"(x));
    return __uint_as_float(r);
}

// ---------------------------------------------------------------------------
// Scratch (device globals)
// ---------------------------------------------------------------------------
__device__ float g_hst[M_ROWS * HID];              // hs, tf32-rounded
__device__ float g_wt[4 * HID * NHD];              // W^T [N][K], tf32-rounded
__device__ __nv_bfloat16 g_qhi[M_ROWS * NHD];
__device__ __nv_bfloat16 g_qlo[M_ROWS * NHD];
__device__ __nv_bfloat16 g_khi[M_ROWS * NHD];
__device__ __nv_bfloat16 g_klo[M_ROWS * NHD];
__device__ __nv_bfloat16 g_vhi[M_ROWS * NHD];
__device__ __nv_bfloat16 g_vlo[M_ROWS * NHD];
__device__ float g_att[M_ROWS * NHD];              // attention out, tf32-rounded

// ---------------------------------------------------------------------------
// Pre-pass 1: hs -> tf32-rounded fp32
// ---------------------------------------------------------------------------
__global__ void hsround_kernel(const float* __restrict__ x, float* __restrict__ y, int n4)
{
    int i = blockIdx.x * blockDim.x + threadIdx.x;
    if (i >= n4) return;
    const float4 v = ((const float4*)x)[i];
    ((float4*)y)[i] = make_float4(rna_tf32(v.x), rna_tf32(v.y),
                                  rna_tf32(v.z), rna_tf32(v.w));
}

// ---------------------------------------------------------------------------
// Pre-pass 2: W[K,N] -> Wt[N,K] tf32-rounded fp32 (32x32 smem tiles)
// ---------------------------------------------------------------------------
__global__ void wt_kernel(const float* __restrict__ W0, const float* __restrict__ W1,
                          const float* __restrict__ W2, const float* __restrict__ W3,
                          float* __restrict__ wt)
{
    const int z = blockIdx.z;
    const float* W = (z == 0) ? W0 : (z == 1) ? W1 : (z == 2) ? W2 : W3;
    __shared__ float t[32][33];
    const int n0 = blockIdx.x * 32, k0 = blockIdx.y * 32;
    const int tx = threadIdx.x, ty = threadIdx.y;
#pragma unroll
    for (int i = 0; i < 4; i++)
        t[ty + 8 * i][tx] = W[(size_t)(k0 + ty + 8 * i) * NHD + n0 + tx];
    __syncthreads();
    const size_t zo = (size_t)z * HID * NHD;
#pragma unroll
    for (int i = 0; i < 4; i++)
        wt[zo + (size_t)(n0 + ty + 8 * i) * KDIM + k0 + tx] = rna_tf32(t[tx][ty + 8 * i]);
}

// ---------------------------------------------------------------------------
// TF32 single-pass GEMM: C[M,N] = A[M,K] @ B[N,K]^T, fp32(tf32) operands.
// CTA 128x128, 4 warps (64x64 warp tiles), BK=32, 2-stage cp.async,
// 72KB smem -> 2 CTAs/SM. 144B padded rows (9x16B, odd -> conflict-free).
// m16n8k8 tf32 MMA; A frags via standard ldm4 lane map, B via n/k permuted map.
// ---------------------------------------------------------------------------
#define BK        32
#define NITER     (KDIM / BK)           // 64
#define STR_B     144                   // 32 floats (128B) + 16B pad
#define TILE_B    (128 * STR_B)         // 18432
#define OFF_A     0
#define OFF_B     TILE_B
#define STAGE_B   (2 * TILE_B)          // 36864
#define GEMM_SMEM (2 * STAGE_B)         // 73728

struct GemmPtrs {
    const float *A, *B;
    float* C;
    __nv_bfloat16 *Chi, *Clo;
    float cscale;
};

__device__ __forceinline__ void gemm_copy_stage(
    uint32_t sdst, const GemmPtrs& g, int m0, int n0, int kb, int tid)
{
    // 2048 x 16B chunks: A 1024 (128 rows x 8 units), B 1024; 16 per thread
#pragma unroll
    for (int i = 0; i < 16; i++) {
        const int idx = tid + i * 128;
        const int mat = idx >> 10, rem = idx & 1023;
        const int row = rem >> 3, unit = rem & 7;
        const float* sp = (mat == 0)
            ? g.A + (size_t)(m0 + row) * KDIM + kb + unit * 4
            : g.B + (size_t)(n0 + row) * KDIM + kb + unit * 4;
        CP_ASYNC16(sdst + mat * TILE_B + row * STR_B + unit * 16, sp);
    }
    CP_COMMIT();
}

template <bool SPLIT>
__device__ __forceinline__ void gemm_body_tf32(const GemmPtrs& g)
{
    extern __shared__ __align__(128) char smem[];
    const uint32_t sbase = smem_u32(smem);
    const int tid = threadIdx.x, wid = tid >> 5, lane = tid & 31;
    const int m0 = blockIdx.y * 128, n0 = blockIdx.x * 128;
    const int wm = wid & 1, wn = wid >> 1;

    float acc[4][8][4];
#pragma unroll
    for (int a = 0; a < 4; a++)
#pragma unroll
        for (int b = 0; b < 8; b++)
#pragma unroll
            for (int c = 0; c < 4; c++) acc[a][b][c] = 0.f;

    // A lane map: lanes 0-15 -> rows 0-15 (+0B), lanes 16-31 -> rows 0-15 (+16B)
    const uint32_t alofs = (uint32_t)((lane & 15) * STR_B + (lane >> 4) * 16);
    // B lane map: lanes 0-7 rows0-7 +0; 8-15 rows0-7 +16; 16-23 rows8-15 +0; 24-31 rows8-15 +16
    const uint32_t blofs = (uint32_t)((((lane & 7) + ((lane >> 4) << 3)) * STR_B) +
                                      (((lane >> 3) & 1) * 16));

    gemm_copy_stage(sbase, g, m0, n0, 0, tid);

    for (int t = 0; t < NITER; ++t) {
        if (t + 1 < NITER) {
            gemm_copy_stage(sbase + ((t + 1) & 1) * STAGE_B, g, m0, n0, (t + 1) * BK, tid);
            CP_WAIT(1);
        } else {
            CP_WAIT(0);
        }
        __syncthreads();

        const uint32_t s0 = sbase + (t & 1) * STAGE_B;
#pragma unroll
        for (int ks = 0; ks < 4; ++ks) {          // k8 steps within BK=32
            const uint32_t kb = (uint32_t)(ks * 32);   // 8 floats
            uint32_t Af[4][4];
#pragma unroll
            for (int mf = 0; mf < 4; mf++)
                ldm4(Af[mf], s0 + OFF_A + (uint32_t)((wm * 64 + mf * 16) * STR_B) + kb + alofs);
#pragma unroll
            for (int np = 0; np < 4; np++) {
                uint32_t Bf[4];
                ldm4(Bf, s0 + OFF_B + (uint32_t)((wn * 64 + np * 16) * STR_B) + kb + blofs);
#pragma unroll
                for (int mf = 0; mf < 4; mf++) {
                    mma_tf32(acc[mf][np * 2],     Af[mf], Bf[0], Bf[1]);
                    mma_tf32(acc[mf][np * 2 + 1], Af[mf], Bf[2], Bf[3]);
                }
            }
        }
        __syncthreads();
    }

    const int gq = lane >> 2, tig = lane & 3;
#pragma unroll
    for (int mf = 0; mf < 4; mf++) {
        const int row = m0 + wm * 64 + mf * 16 + gq;
#pragma unroll
        for (int nf = 0; nf < 8; nf++) {
            const int col = n0 + wn * 64 + nf * 8 + tig * 2;
            if (SPLIT) {
#pragma unroll
                for (int half = 0; half < 2; half++) {
                    const size_t off = (size_t)(row + half * 8) * 2048 + col;
                    const float x0 = acc[mf][nf][half * 2] * g.cscale;
                    const float x1 = acc[mf][nf][half * 2 + 1] * g.cscale;
                    const __nv_bfloat16 h0 = __float2bfloat16(x0), h1 = __float2bfloat16(x1);
                    const __nv_bfloat16 l0 = __float2bfloat16(x0 - __bfloat162float(h0));
                    const __nv_bfloat16 l1 = __float2bfloat16(x1 - __bfloat162float(h1));
                    *(__nv_bfloat162*)&g.Chi[off] = __nv_bfloat162(h0, h1);
                    *(__nv_bfloat162*)&g.Clo[off] = __nv_bfloat162(l0, l1);
                }
            } else {
                *(float2*)&g.C[(size_t)row * 2048 + col] =
                    make_float2(acc[mf][nf][0], acc[mf][nf][1]);
                *(float2*)&g.C[(size_t)(row + 8) * 2048 + col] =
                    make_float2(acc[mf][nf][2], acc[mf][nf][3]);
            }
        }
    }
}

__global__ __launch_bounds__(128, 2) void qkv_tf32_kernel(
    const float* __restrict__ A, const float* __restrict__ Wt,
    __nv_bfloat16* __restrict__ Qh, __nv_bfloat16* __restrict__ Ql,
    __nv_bfloat16* __restrict__ Kh, __nv_bfloat16* __restrict__ Kl,
    __nv_bfloat16* __restrict__ Vh, __nv_bfloat16* __restrict__ Vl)
{
    const size_t WSZ = (size_t)HID * NHD;
    const int z = blockIdx.z;
    GemmPtrs g;
    g.A = A;
    g.B = Wt + (size_t)z * WSZ;
    g.C = nullptr;
    g.Chi = (z == 0) ? Qh : (z == 1) ? Kh : Vh;
    g.Clo = (z == 0) ? Ql : (z == 1) ? Kl : Vl;
    g.cscale = (z == 0) ? SCALE_F : 1.0f;   // fold softmax scale into Q (exact: 2^-3)
    gemm_body_tf32<true>(g);
}

__global__ __launch_bounds__(128, 2) void out_tf32_kernel(
    const float* __restrict__ A, const float* __restrict__ Wt,
    float* __restrict__ C)
{
    GemmPtrs g;
    g.A = A; g.B = Wt; g.C = C; g.Chi = nullptr; g.Clo = nullptr; g.cscale = 1.0f;
    gemm_body_tf32<false>(g);
}

// ---------------------------------------------------------------------------
// Tensor-core flash attention (split-bf16, 3 products), single-buffered
// (proven config). Scale pre-folded into Q. Emits tf32-rounded fp32 output.
// ---------------------------------------------------------------------------
#define ASTRB   144
#define AQH     0
#define AQL     18432
#define AKH     36864
#define AKL     55296
#define AVH     73728
#define AVL     92160
#define ATT_SMEM 110592

__device__ __forceinline__ int token_of(int tile, int jj)
{
    return ((tile >> 2) << 9) + ((jj >> 4) << 6) + ((tile & 3) << 4) + (jj & 15);
}

__global__ __launch_bounds__(256, 1) void attn_mma_kernel(
    const __nv_bfloat16* __restrict__ Qhi, const __nv_bfloat16* __restrict__ Qlo,
    const __nv_bfloat16* __restrict__ Khi, const __nv_bfloat16* __restrict__ Klo,
    const __nv_bfloat16* __restrict__ Vhi, const __nv_bfloat16* __restrict__ Vlo,
    float* __restrict__ Att)
{
    extern __shared__ __align__(128) char smem[];
    const uint32_t sbase = smem_u32(smem);
    const int t = blockIdx.x, h = blockIdx.y, b = blockIdx.z;
    const int tid = threadIdx.x, w = tid >> 5, lane = tid & 31;
    const size_t base = (size_t)b * S_SZ * NHD + (size_t)h * HD;

    const int tr = t >> 2, tc = t & 3;
    const int cr = min(max(tr, 1), 7);
    const int cc = min(max(tc, 1), 3);
    int kts[NKV];
    kts[0] = (cr - 1) * 4 + (cc - 1);
    kts[1] = (cr - 1) * 4 + cc;
    kts[2] = cr * 4 + (cc - 1);
    kts[3] = cr * 4 + cc;

    for (int i = tid; i < 2048; i += 256) {
        const int mat = i >> 10, rem = i & 1023;
        const int row = rem >> 3, c = rem & 7;
        const int qs = token_of(t, row);
        const __nv_bfloat16* src = (mat ? Qlo : Qhi) + base + (size_t)qs * NHD + c * 8;
        CP_ASYNC16(sbase + (mat ? AQL : AQH) + row * ASTRB + c * 16, src);
    }
    CP_COMMIT();
    CP_WAIT(0);
    __syncthreads();

    uint32_t qh[4][4], ql[4][4];
    const uint32_t qoff = (uint32_t)((w * 16 + (lane & 15)) * ASTRB + (lane >> 4) * 16);
#pragma unroll
    for (int kf = 0; kf < 4; kf++) {
        ldm4(qh[kf], sbase + AQH + qoff + kf * 32);
        ldm4(ql[kf], sbase + AQL + qoff + kf * 32);
    }

    float O[8][4];
#pragma unroll
    for (int nf = 0; nf < 8; nf++)
#pragma unroll
        for (int c = 0; c < 4; c++) O[nf][c] = 0.f;
    float m0 = -1e30f, m1 = -1e30f, l0 = 0.f, l1 = 0.f;

    for (int w4 = 0; w4 < NKV; ++w4) {
        const int kt = kts[w4];
        __syncthreads();
        for (int i = tid; i < 4096; i += 256) {
            const int mat = i >> 10, rem = i & 1023;
            const int row = rem >> 3, c = rem & 7;
            const int ks = token_of(kt, row);
            const size_t off = base + (size_t)ks * NHD + c * 8;
            const __nv_bfloat16* src =
                (mat == 0) ? Khi + off : (mat == 1) ? Klo + off :
                (mat == 2) ? Vhi + off : Vlo + off;
            const uint32_t doff = (mat == 0) ? AKH : (mat == 1) ? AKL :
                                  (mat == 2) ? AVH : AVL;
            CP_ASYNC16(sbase + doff + row * ASTRB + c * 16, src);
        }
        CP_COMMIT();
        CP_WAIT(0);
        __syncthreads();

        // ---- S = Q @ K^T (scale already folded into Q) ----
        float S[16][4];
#pragma unroll
        for (int nf = 0; nf < 16; nf++)
#pragma unroll
            for (int c = 0; c < 4; c++) S[nf][c] = 0.f;

#pragma unroll
        for (int kf = 0; kf < 4; kf++) {
#pragma unroll
            for (int g = 0; g < 8; g++) {
                uint32_t kh[4], kl[4];
                const uint32_t ko = (uint32_t)((g * 16 + (lane & 15)) * ASTRB +
                                               (lane >> 4) * 16 + kf * 32);
                ldm4(kh, sbase + AKH + ko);
                mma_bf16(S[2 * g],     qh[kf], kh[0], kh[2]);
                mma_bf16(S[2 * g + 1], qh[kf], kh[1], kh[3]);
                ldm4(kl, sbase + AKL + ko);
                mma_bf16(S[2 * g],     qh[kf], kl[0], kl[2]);
                mma_bf16(S[2 * g + 1], qh[kf], kl[1], kl[3]);
                mma_bf16(S[2 * g],     ql[kf], kh[0], kh[2]);
                mma_bf16(S[2 * g + 1], ql[kf], kh[1], kh[3]);
            }
        }

        // ---- online softmax ----
        float tmax0 = -1e30f, tmax1 = -1e30f;
#pragma unroll
        for (int nf = 0; nf < 16; nf++) {
            tmax0 = fmaxf(tmax0, fmaxf(S[nf][0], S[nf][1]));
            tmax1 = fmaxf(tmax1, fmaxf(S[nf][2], S[nf][3]));
        }
        tmax0 = fmaxf(tmax0, __shfl_xor_sync(0xFFFFFFFF, tmax0, 1));
        tmax0 = fmaxf(tmax0, __shfl_xor_sync(0xFFFFFFFF, tmax0, 2));
        tmax1 = fmaxf(tmax1, __shfl_xor_sync(0xFFFFFFFF, tmax1, 1));
        tmax1 = fmaxf(tmax1, __shfl_xor_sync(0xFFFFFFFF, tmax1, 2));

        const float mn0 = fmaxf(m0, tmax0), mn1 = fmaxf(m1, tmax1);
        const float a0 = __expf(m0 - mn0), a1 = __expf(m1 - mn1);
        m0 = mn0; m1 = mn1;
        l0 *= a0; l1 *= a1;
#pragma unroll
        for (int nf = 0; nf < 8; nf++) {
            O[nf][0] *= a0; O[nf][1] *= a0;
            O[nf][2] *= a1; O[nf][3] *= a1;
        }
        float ls0 = 0.f, ls1 = 0.f;
#pragma unroll
        for (int nf = 0; nf < 16; nf++) {
            S[nf][0] = __expf(S[nf][0] - m0); ls0 += S[nf][0];
            S[nf][1] = __expf(S[nf][1] - m0); ls0 += S[nf][1];
            S[nf][2] = __expf(S[nf][2] - m1); ls1 += S[nf][2];
            S[nf][3] = __expf(S[nf][3] - m1); ls1 += S[nf][3];
        }
        l0 += ls0; l1 += ls1;

        // ---- O += P @ V; P hi via truncation mask, residual exact ----
#pragma unroll
        for (int kf = 0; kf < 8; kf++) {
            uint32_t ph[4], pl[4];
            {
                const float* sA = S[2 * kf];
                const float* sB = S[2 * kf + 1];
                const uint32_t uA0 = __float_as_uint(sA[0]), uA1 = __float_as_uint(sA[1]);
                const uint32_t uA2 = __float_as_uint(sA[2]), uA3 = __float_as_uint(sA[3]);
                const uint32_t uB0 = __float_as_uint(sB[0]), uB1 = __float_as_uint(sB[1]);
                const uint32_t uB2 = __float_as_uint(sB[2]), uB3 = __float_as_uint(sB[3]);
                ph[0] = __byte_perm(uA0, uA1, 0x7632);
                ph[1] = __byte_perm(uA2, uA3, 0x7632);
                ph[2] = __byte_perm(uB0, uB1, 0x7632);
                ph[3] = __byte_perm(uB2, uB3, 0x7632);
                pl[0] = pkbf(sA[0] - __uint_as_float(uA0 & 0xFFFF0000u),
                             sA[1] - __uint_as_float(uA1 & 0xFFFF0000u));
                pl[1] = pkbf(sA[2] - __uint_as_float(uA2 & 0xFFFF0000u),
                             sA[3] - __uint_as_float(uA3 & 0xFFFF0000u));
                pl[2] = pkbf(sB[0] - __uint_as_float(uB0 & 0xFFFF0000u),
                             sB[1] - __uint_as_float(uB1 & 0xFFFF0000u));
                pl[3] = pkbf(sB[2] - __uint_as_float(uB2 & 0xFFFF0000u),
                             sB[3] - __uint_as_float(uB3 & 0xFFFF0000u));
            }
#pragma unroll
            for (int nv = 0; nv < 4; nv++) {
                uint32_t vh[4], vl[4];
                const uint32_t vo = (uint32_t)((kf * 16 + (lane & 15)) * ASTRB +
                                               (lane >> 4) * 16 + nv * 32);
                ldm4t(vh, sbase + AVH + vo);
                mma_bf16(O[2 * nv],     ph, vh[0], vh[1]);
                mma_bf16(O[2 * nv + 1], ph, vh[2], vh[3]);
                ldm4t(vl, sbase + AVL + vo);
                mma_bf16(O[2 * nv],     ph, vl[0], vl[1]);
                mma_bf16(O[2 * nv + 1], ph, vl[2], vl[3]);
                mma_bf16(O[2 * nv],     pl, vh[0], vh[1]);
                mma_bf16(O[2 * nv + 1], pl, vh[2], vh[3]);
            }
        }
    }

    l0 += __shfl_xor_sync(0xFFFFFFFF, l0, 1);
    l0 += __shfl_xor_sync(0xFFFFFFFF, l0, 2);
    l1 += __shfl_xor_sync(0xFFFFFFFF, l1, 1);
    l1 += __shfl_xor_sync(0xFFFFFFFF, l1, 2);
    const float inv0 = 1.f / l0, inv1 = 1.f / l1;
    const int gq = lane >> 2, tig = lane & 3;
    const int qs0 = token_of(t, w * 16 + gq);
    const int qs1 = token_of(t, w * 16 + gq + 8);
    const size_t r0 = base + (size_t)qs0 * NHD;
    const size_t r1 = base + (size_t)qs1 * NHD;
#pragma unroll
    for (int nf = 0; nf < 8; nf++) {
        const int col = nf * 8 + tig * 2;
        *(float2*)&Att[r0 + col] = make_float2(rna_tf32(O[nf][0] * inv0),
                                               rna_tf32(O[nf][1] * inv0));
        *(float2*)&Att[r1 + col] = make_float2(rna_tf32(O[nf][2] * inv1),
                                               rna_tf32(O[nf][3] * inv1));
    }
}

// ---------------------------------------------------------------------------
// Launch
// ---------------------------------------------------------------------------
extern "C" void kernel_launch(void* const* d_in, const int* in_sizes, int n_in,
                              void* d_out, int out_size)
{
    const float* hs = (const float*)d_in[0];
    const float* Wq = (const float*)d_in[1];
    const float* Wk = (const float*)d_in[2];
    const float* Wv = (const float*)d_in[3];
    const float* Wo = (const float*)d_in[4];
    float* out = (float*)d_out;

    float *hst, *wt, *att;
    __nv_bfloat16 *qhi, *qlo, *khi, *klo, *vhi, *vlo;
    cudaGetSymbolAddress((void**)&hst, g_hst);
    cudaGetSymbolAddress((void**)&wt, g_wt);
    cudaGetSymbolAddress((void**)&att, g_att);
    cudaGetSymbolAddress((void**)&qhi, g_qhi);
    cudaGetSymbolAddress((void**)&qlo, g_qlo);
    cudaGetSymbolAddress((void**)&khi, g_khi);
    cudaGetSymbolAddress((void**)&klo, g_klo);
    cudaGetSymbolAddress((void**)&vhi, g_vhi);
    cudaGetSymbolAddress((void**)&vlo, g_vlo);

    cudaFuncSetAttribute(qkv_tf32_kernel, cudaFuncAttributeMaxDynamicSharedMemorySize, GEMM_SMEM);
    cudaFuncSetAttribute(out_tf32_kernel, cudaFuncAttributeMaxDynamicSharedMemorySize, GEMM_SMEM);
    cudaFuncSetAttribute(attn_mma_kernel, cudaFuncAttributeMaxDynamicSharedMemorySize, ATT_SMEM);

    const int n4 = (M_ROWS * HID) / 4;
    hsround_kernel<<<(n4 + 255) / 256, 256>>>(hs, hst, n4);
    wt_kernel<<<dim3(NHD / 32, HID / 32, 4), dim3(32, 8)>>>(Wq, Wk, Wv, Wo, wt);

    qkv_tf32_kernel<<<dim3(NHD / 128, M_ROWS / 128, 3), 128, GEMM_SMEM>>>(
        hst, wt, qhi, qlo, khi, klo, vhi, vlo);

    attn_mma_kernel<<<dim3(NT, NH, B_SZ), 256, ATT_SMEM>>>(
        qhi, qlo, khi, klo, vhi, vlo, att);

    const size_t WSZ = (size_t)HID * NHD;
    out_tf32_kernel<<<dim3(HID / 128, M_ROWS / 128), 128, GEMM_SMEM>>>(
        att, wt + 3 * WSZ, out);
}

// round 13
// speedup vs baseline: 2.3312x; 1.0758x over previous
#include <cuda_runtime.h>
#include <cuda_bf16.h>
#include <cstdint>
#include <cstddef>

// ---------------------------------------------------------------------------
// Problem constants
// ---------------------------------------------------------------------------
#define B_SZ   2
#define S_SZ   4096
#define HID    2048
#define NH     32
#define HD     64
#define NHD    2048
#define M_ROWS (B_SZ * S_SZ)       // 8192
#define NT     32
#define NKV    4
#define SCALE_F 0.125f
#define KDIM   2048

// ---------------------------------------------------------------------------
// PTX helpers (plain sm_80+ features only)
// ---------------------------------------------------------------------------
__device__ __forceinline__ uint32_t smem_u32(const void* p) {
    uint32_t a;
    asm("{ .reg .u64 t; cvta.to.shared.u64 t, %1; cvt.u32.u64 %0, t; }" : "=r"(a) : "l"(p));
    return a;
}
#define CP_ASYNC16(dst, src) \
    asm volatile("cp.async.cg.shared.global [%0], [%1], 16;" :: "r"(dst), "l"(src) : "memory")
#define CP_COMMIT()  asm volatile("cp.async.commit_group;" ::: "memory")
#define CP_WAIT(n)   asm volatile("cp.async.wait_group %0;" :: "n"(n) : "memory")

__device__ __forceinline__ void ldm4(uint32_t* r, uint32_t addr) {
    asm volatile("ldmatrix.sync.aligned.m8n8.x4.shared.b16 {%0,%1,%2,%3}, [%4];"
        : "=r"(r[0]), "=r"(r[1]), "=r"(r[2]), "=r"(r[3]) : "r"(addr));
}
__device__ __forceinline__ void ldm4t(uint32_t* r, uint32_t addr) {
    asm volatile("ldmatrix.sync.aligned.m8n8.x4.trans.shared.b16 {%0,%1,%2,%3}, [%4];"
        : "=r"(r[0]), "=r"(r[1]), "=r"(r[2]), "=r"(r[3]) : "r"(addr));
}
__device__ __forceinline__ void mma_bf16(float* d, const uint32_t* a, uint32_t b0, uint32_t b1) {
    asm volatile("mma.sync.aligned.m16n8k16.row.col.f32.bf16.bf16.f32 "
        "{%0,%1,%2,%3}, {%4,%5,%6,%7}, {%8,%9}, {%0,%1,%2,%3};"
        : "+f"(d[0]), "+f"(d[1]), "+f"(d[2]), "+f"(d[3])
        : "r"(a[0]), "r"(a[1]), "r"(a[2]), "r"(a[3]), "r"(b0), "r"(b1));
}
__device__ __forceinline__ void mma_tf32(float* d, const uint32_t* a, uint32_t b0, uint32_t b1) {
    asm volatile("mma.sync.aligned.m16n8k8.row.col.f32.tf32.tf32.f32 "
        "{%0,%1,%2,%3}, {%4,%5,%6,%7}, {%8,%9}, {%0,%1,%2,%3};"
        : "+f"(d[0]), "+f"(d[1]), "+f"(d[2]), "+f"(d[3])
        : "r"(a[0]), "r"(a[1]), "r"(a[2]), "r"(a[3]), "r"(b0), "r"(b1));
}
__device__ __forceinline__ uint32_t pkbf(float a, float b) {
    __nv_bfloat162 t(__float2bfloat16(a), __float2bfloat16(b));
    return *(uint32_t*)&t;
}
__device__ __forceinline__ float rna_tf32(float x) {
    uint32_t r;
    asm("cvt.rna.tf32.f32 %0, %1;" : "=r"(r) : "f"(x));
    return __uint_as_float(r);
}

// ---------------------------------------------------------------------------
// Scratch (device globals)
// ---------------------------------------------------------------------------
__device__ float g_hst[M_ROWS * HID];              // hs, tf32-rounded
__device__ float g_wt[4 * HID * NHD];              // W^T [N][K], tf32-rounded
__device__ float g_q[M_ROWS * NHD];                // Q (scaled, tf32-rounded)
__device__ float g_k[M_ROWS * NHD];                // K (tf32-rounded)
__device__ __nv_bfloat16 g_vhi[M_ROWS * NHD];
__device__ __nv_bfloat16 g_vlo[M_ROWS * NHD];
__device__ float g_att[M_ROWS * NHD];              // attention out, tf32-rounded

// ---------------------------------------------------------------------------
// Pre-pass 1: hs -> tf32-rounded fp32
// ---------------------------------------------------------------------------
__global__ void hsround_kernel(const float* __restrict__ x, float* __restrict__ y, int n4)
{
    int i = blockIdx.x * blockDim.x + threadIdx.x;
    if (i >= n4) return;
    const float4 v = ((const float4*)x)[i];
    ((float4*)y)[i] = make_float4(rna_tf32(v.x), rna_tf32(v.y),
                                  rna_tf32(v.z), rna_tf32(v.w));
}

// ---------------------------------------------------------------------------
// Pre-pass 2: W[K,N] -> Wt[N,K] tf32-rounded fp32 (32x32 smem tiles)
// ---------------------------------------------------------------------------
__global__ void wt_kernel(const float* __restrict__ W0, const float* __restrict__ W1,
                          const float* __restrict__ W2, const float* __restrict__ W3,
                          float* __restrict__ wt)
{
    const int z = blockIdx.z;
    const float* W = (z == 0) ? W0 : (z == 1) ? W1 : (z == 2) ? W2 : W3;
    __shared__ float t[32][33];
    const int n0 = blockIdx.x * 32, k0 = blockIdx.y * 32;
    const int tx = threadIdx.x, ty = threadIdx.y;
#pragma unroll
    for (int i = 0; i < 4; i++)
        t[ty + 8 * i][tx] = W[(size_t)(k0 + ty + 8 * i) * NHD + n0 + tx];
    __syncthreads();
    const size_t zo = (size_t)z * HID * NHD;
#pragma unroll
    for (int i = 0; i < 4; i++)
        wt[zo + (size_t)(n0 + ty + 8 * i) * KDIM + k0 + tx] = rna_tf32(t[tx][ty + 8 * i]);
}

// ---------------------------------------------------------------------------
// TF32 single-pass GEMM: C[M,N] = A[M,K] @ B[N,K]^T  (R12-validated).
// CTA 128x128, 4 warps (64x64), BK=32, 2-stage cp.async, 72KB -> 2 CTAs/SM.
// Epilogue modes: 0 raw fp32, 1 rna-fp32 (*cscale), 2 bf16 hi/lo split.
// ---------------------------------------------------------------------------
#define BK        32
#define NITER     (KDIM / BK)           // 64
#define STR_B     144                   // 32 floats + 16B pad
#define TILE_B    (128 * STR_B)         // 18432
#define OFF_A     0
#define OFF_B     TILE_B
#define STAGE_B   (2 * TILE_B)          // 36864
#define GEMM_SMEM (2 * STAGE_B)         // 73728

struct GemmPtrs {
    const float *A, *B;
    float* C;
    __nv_bfloat16 *Chi, *Clo;
    float cscale;
};

__device__ __forceinline__ void gemm_copy_stage(
    uint32_t sdst, const GemmPtrs& g, int m0, int n0, int kb, int tid)
{
#pragma unroll
    for (int i = 0; i < 16; i++) {
        const int idx = tid + i * 128;
        const int mat = idx >> 10, rem = idx & 1023;
        const int row = rem >> 3, unit = rem & 7;
        const float* sp = (mat == 0)
            ? g.A + (size_t)(m0 + row) * KDIM + kb + unit * 4
            : g.B + (size_t)(n0 + row) * KDIM + kb + unit * 4;
        CP_ASYNC16(sdst + mat * TILE_B + row * STR_B + unit * 16, sp);
    }
    CP_COMMIT();
}

template <int MODE>
__device__ __forceinline__ void gemm_body_tf32(const GemmPtrs& g)
{
    extern __shared__ __align__(128) char smem[];
    const uint32_t sbase = smem_u32(smem);
    const int tid = threadIdx.x, wid = tid >> 5, lane = tid & 31;
    const int m0 = blockIdx.y * 128, n0 = blockIdx.x * 128;
    const int wm = wid & 1, wn = wid >> 1;

    float acc[4][8][4];
#pragma unroll
    for (int a = 0; a < 4; a++)
#pragma unroll
        for (int b = 0; b < 8; b++)
#pragma unroll
            for (int c = 0; c < 4; c++) acc[a][b][c] = 0.f;

    const uint32_t alofs = (uint32_t)((lane & 15) * STR_B + (lane >> 4) * 16);
    const uint32_t blofs = (uint32_t)((((lane & 7) + ((lane >> 4) << 3)) * STR_B) +
                                      (((lane >> 3) & 1) * 16));

    gemm_copy_stage(sbase, g, m0, n0, 0, tid);

    for (int t = 0; t < NITER; ++t) {
        if (t + 1 < NITER) {
            gemm_copy_stage(sbase + ((t + 1) & 1) * STAGE_B, g, m0, n0, (t + 1) * BK, tid);
            CP_WAIT(1);
        } else {
            CP_WAIT(0);
        }
        __syncthreads();

        const uint32_t s0 = sbase + (t & 1) * STAGE_B;
#pragma unroll
        for (int ks = 0; ks < 4; ++ks) {
            const uint32_t kb = (uint32_t)(ks * 32);
            uint32_t Af[4][4];
#pragma unroll
            for (int mf = 0; mf < 4; mf++)
                ldm4(Af[mf], s0 + OFF_A + (uint32_t)((wm * 64 + mf * 16) * STR_B) + kb + alofs);
#pragma unroll
            for (int np = 0; np < 4; np++) {
                uint32_t Bf[4];
                ldm4(Bf, s0 + OFF_B + (uint32_t)((wn * 64 + np * 16) * STR_B) + kb + blofs);
#pragma unroll
                for (int mf = 0; mf < 4; mf++) {
                    mma_tf32(acc[mf][np * 2],     Af[mf], Bf[0], Bf[1]);
                    mma_tf32(acc[mf][np * 2 + 1], Af[mf], Bf[2], Bf[3]);
                }
            }
        }
        __syncthreads();
    }

    const int gq = lane >> 2, tig = lane & 3;
#pragma unroll
    for (int mf = 0; mf < 4; mf++) {
        const int row = m0 + wm * 64 + mf * 16 + gq;
#pragma unroll
        for (int nf = 0; nf < 8; nf++) {
            const int col = n0 + wn * 64 + nf * 8 + tig * 2;
            if (MODE == 2) {
#pragma unroll
                for (int half = 0; half < 2; half++) {
                    const size_t off = (size_t)(row + half * 8) * 2048 + col;
                    const float x0 = acc[mf][nf][half * 2];
                    const float x1 = acc[mf][nf][half * 2 + 1];
                    const __nv_bfloat16 h0 = __float2bfloat16(x0), h1 = __float2bfloat16(x1);
                    const __nv_bfloat16 l0 = __float2bfloat16(x0 - __bfloat162float(h0));
                    const __nv_bfloat16 l1 = __float2bfloat16(x1 - __bfloat162float(h1));
                    *(__nv_bfloat162*)&g.Chi[off] = __nv_bfloat162(h0, h1);
                    *(__nv_bfloat162*)&g.Clo[off] = __nv_bfloat162(l0, l1);
                }
            } else if (MODE == 1) {
#pragma unroll
                for (int half = 0; half < 2; half++) {
                    const size_t off = (size_t)(row + half * 8) * 2048 + col;
                    *(float2*)&g.C[off] = make_float2(
                        rna_tf32(acc[mf][nf][half * 2] * g.cscale),
                        rna_tf32(acc[mf][nf][half * 2 + 1] * g.cscale));
                }
            } else {
                *(float2*)&g.C[(size_t)row * 2048 + col] =
                    make_float2(acc[mf][nf][0], acc[mf][nf][1]);
                *(float2*)&g.C[(size_t)(row + 8) * 2048 + col] =
                    make_float2(acc[mf][nf][2], acc[mf][nf][3]);
            }
        }
    }
}

__global__ __launch_bounds__(128, 2) void qkv_tf32_kernel(
    const float* __restrict__ A, const float* __restrict__ Wt,
    float* __restrict__ Q, float* __restrict__ K,
    __nv_bfloat16* __restrict__ Vh, __nv_bfloat16* __restrict__ Vl)
{
    const size_t WSZ = (size_t)HID * NHD;
    const int z = blockIdx.z;
    GemmPtrs g;
    g.A = A;
    g.B = Wt + (size_t)z * WSZ;
    g.C = (z == 0) ? Q : K;
    g.Chi = Vh; g.Clo = Vl;
    g.cscale = (z == 0) ? SCALE_F : 1.0f;   // fold softmax scale into Q (exact: 2^-3)
    if (z == 2) gemm_body_tf32<2>(g);       // V: bf16 hi/lo (PV stays bf16-3)
    else        gemm_body_tf32<1>(g);       // Q,K: rna-fp32 for tf32 QK
}

__global__ __launch_bounds__(128, 2) void out_tf32_kernel(
    const float* __restrict__ A, const float* __restrict__ Wt,
    float* __restrict__ C)
{
    GemmPtrs g;
    g.A = A; g.B = Wt; g.C = C; g.Chi = nullptr; g.Clo = nullptr; g.cscale = 1.0f;
    gemm_body_tf32<0>(g);
}

// ---------------------------------------------------------------------------
// Flash attention: QK in tf32 (GEMM-validated maps), PV in split-bf16.
// Smem: Q fp32 + K fp32 (272B rows) + V hi/lo bf16 (144B rows) = 104KB.
// ---------------------------------------------------------------------------
#define STRQ    272
#define ASTRB   144
#define AQ_O    0
#define AK_O    34816
#define AVH     69632
#define AVL     88064
#define ATT_SMEM 106496

__device__ __forceinline__ int token_of(int tile, int jj)
{
    return ((tile >> 2) << 9) + ((jj >> 4) << 6) + ((tile & 3) << 4) + (jj & 15);
}

__global__ __launch_bounds__(256, 1) void attn_mma_kernel(
    const float* __restrict__ Qg, const float* __restrict__ Kg,
    const __nv_bfloat16* __restrict__ Vhi, const __nv_bfloat16* __restrict__ Vlo,
    float* __restrict__ Att)
{
    extern __shared__ __align__(128) char smem[];
    const uint32_t sbase = smem_u32(smem);
    const int t = blockIdx.x, h = blockIdx.y, b = blockIdx.z;
    const int tid = threadIdx.x, w = tid >> 5, lane = tid & 31;
    const size_t base = (size_t)b * S_SZ * NHD + (size_t)h * HD;

    const int tr = t >> 2, tc = t & 3;
    const int cr = min(max(tr, 1), 7);
    const int cc = min(max(tc, 1), 3);
    int kts[NKV];
    kts[0] = (cr - 1) * 4 + (cc - 1);
    kts[1] = (cr - 1) * 4 + cc;
    kts[2] = cr * 4 + (cc - 1);
    kts[3] = cr * 4 + cc;

    // Q tile (fp32, 128 rows x 16 chunks)
    for (int i = tid; i < 2048; i += 256) {
        const int row = i >> 4, c = i & 15;
        const int qs = token_of(t, row);
        CP_ASYNC16(sbase + AQ_O + row * STRQ + c * 16, Qg + base + (size_t)qs * NHD + c * 4);
    }
    CP_COMMIT();
    CP_WAIT(0);
    __syncthreads();

    // Q fragments: 8 k8-steps, resident for all tiles
    uint32_t qf[8][4];
    const uint32_t alofs = (uint32_t)((lane & 15) * STRQ + (lane >> 4) * 16);
    const uint32_t qrowoff = (uint32_t)(w * 16 * STRQ);
#pragma unroll
    for (int ks = 0; ks < 8; ks++)
        ldm4(qf[ks], sbase + AQ_O + qrowoff + ks * 32 + alofs);

    // K B-frag lane map (GEMM-validated)
    const uint32_t blofs = (uint32_t)((((lane & 7) + ((lane >> 4) << 3)) * STRQ) +
                                      (((lane >> 3) & 1) * 16));

    float O[8][4];
#pragma unroll
    for (int nf = 0; nf < 8; nf++)
#pragma unroll
        for (int c = 0; c < 4; c++) O[nf][c] = 0.f;
    float m0 = -1e30f, m1 = -1e30f, l0 = 0.f, l1 = 0.f;

    for (int w4 = 0; w4 < NKV; ++w4) {
        const int kt = kts[w4];
        __syncthreads();
        // K fp32 (2048 chunks) + V hi/lo bf16 (2048 chunks)
        for (int i = tid; i < 4096; i += 256) {
            if (i < 2048) {
                const int row = i >> 4, c = i & 15;
                const int ks = token_of(kt, row);
                CP_ASYNC16(sbase + AK_O + row * STRQ + c * 16,
                           Kg + base + (size_t)ks * NHD + c * 4);
            } else {
                const int rem = i - 2048;
                const int sel = rem >> 10, r2 = rem & 1023;
                const int row = r2 >> 3, c = r2 & 7;
                const int ks = token_of(kt, row);
                const __nv_bfloat16* src = (sel ? Vlo : Vhi) + base + (size_t)ks * NHD + c * 8;
                CP_ASYNC16(sbase + (sel ? AVL : AVH) + row * ASTRB + c * 16, src);
            }
        }
        CP_COMMIT();
        CP_WAIT(0);
        __syncthreads();

        // ---- S = Q @ K^T, tf32 (scale folded into Q) ----
        float S[16][4];
#pragma unroll
        for (int nf = 0; nf < 16; nf++)
#pragma unroll
            for (int c = 0; c < 4; c++) S[nf][c] = 0.f;

#pragma unroll
        for (int ks = 0; ks < 8; ks++) {
#pragma unroll
            for (int np = 0; np < 8; np++) {
                uint32_t Bf[4];
                ldm4(Bf, sbase + AK_O + (uint32_t)(np * 16 * STRQ) + ks * 32 + blofs);
                mma_tf32(S[np * 2],     qf[ks], Bf[0], Bf[1]);
                mma_tf32(S[np * 2 + 1], qf[ks], Bf[2], Bf[3]);
            }
        }

        // ---- online softmax ----
        float tmax0 = -1e30f, tmax1 = -1e30f;
#pragma unroll
        for (int nf = 0; nf < 16; nf++) {
            tmax0 = fmaxf(tmax0, fmaxf(S[nf][0], S[nf][1]));
            tmax1 = fmaxf(tmax1, fmaxf(S[nf][2], S[nf][3]));
        }
        tmax0 = fmaxf(tmax0, __shfl_xor_sync(0xFFFFFFFF, tmax0, 1));
        tmax0 = fmaxf(tmax0, __shfl_xor_sync(0xFFFFFFFF, tmax0, 2));
        tmax1 = fmaxf(tmax1, __shfl_xor_sync(0xFFFFFFFF, tmax1, 1));
        tmax1 = fmaxf(tmax1, __shfl_xor_sync(0xFFFFFFFF, tmax1, 2));

        const float mn0 = fmaxf(m0, tmax0), mn1 = fmaxf(m1, tmax1);
        const float a0 = __expf(m0 - mn0), a1 = __expf(m1 - mn1);
        m0 = mn0; m1 = mn1;
        l0 *= a0; l1 *= a1;
#pragma unroll
        for (int nf = 0; nf < 8; nf++) {
            O[nf][0] *= a0; O[nf][1] *= a0;
            O[nf][2] *= a1; O[nf][3] *= a1;
        }
        float ls0 = 0.f, ls1 = 0.f;
#pragma unroll
        for (int nf = 0; nf < 16; nf++) {
            S[nf][0] = __expf(S[nf][0] - m0); ls0 += S[nf][0];
            S[nf][1] = __expf(S[nf][1] - m0); ls0 += S[nf][1];
            S[nf][2] = __expf(S[nf][2] - m1); ls1 += S[nf][2];
            S[nf][3] = __expf(S[nf][3] - m1); ls1 += S[nf][3];
        }
        l0 += ls0; l1 += ls1;

        // ---- O += P @ V (split-bf16, proven); P hi via truncation ----
#pragma unroll
        for (int kf = 0; kf < 8; kf++) {
            uint32_t ph[4], pl[4];
            {
                const float* sA = S[2 * kf];
                const float* sB = S[2 * kf + 1];
                const uint32_t uA0 = __float_as_uint(sA[0]), uA1 = __float_as_uint(sA[1]);
                const uint32_t uA2 = __float_as_uint(sA[2]), uA3 = __float_as_uint(sA[3]);
                const uint32_t uB0 = __float_as_uint(sB[0]), uB1 = __float_as_uint(sB[1]);
                const uint32_t uB2 = __float_as_uint(sB[2]), uB3 = __float_as_uint(sB[3]);
                ph[0] = __byte_perm(uA0, uA1, 0x7632);
                ph[1] = __byte_perm(uA2, uA3, 0x7632);
                ph[2] = __byte_perm(uB0, uB1, 0x7632);
                ph[3] = __byte_perm(uB2, uB3, 0x7632);
                pl[0] = pkbf(sA[0] - __uint_as_float(uA0 & 0xFFFF0000u),
                             sA[1] - __uint_as_float(uA1 & 0xFFFF0000u));
                pl[1] = pkbf(sA[2] - __uint_as_float(uA2 & 0xFFFF0000u),
                             sA[3] - __uint_as_float(uA3 & 0xFFFF0000u));
                pl[2] = pkbf(sB[0] - __uint_as_float(uB0 & 0xFFFF0000u),
                             sB[1] - __uint_as_float(uB1 & 0xFFFF0000u));
                pl[3] = pkbf(sB[2] - __uint_as_float(uB2 & 0xFFFF0000u),
                             sB[3] - __uint_as_float(uB3 & 0xFFFF0000u));
            }
#pragma unroll
            for (int nv = 0; nv < 4; nv++) {
                uint32_t vh[4], vl[4];
                const uint32_t vo = (uint32_t)((kf * 16 + (lane & 15)) * ASTRB +
                                               (lane >> 4) * 16 + nv * 32);
                ldm4t(vh, sbase + AVH + vo);
                mma_bf16(O[2 * nv],     ph, vh[0], vh[1]);
                mma_bf16(O[2 * nv + 1], ph, vh[2], vh[3]);
                ldm4t(vl, sbase + AVL + vo);
                mma_bf16(O[2 * nv],     ph, vl[0], vl[1]);
                mma_bf16(O[2 * nv + 1], ph, vl[2], vl[3]);
                mma_bf16(O[2 * nv],     pl, vh[0], vh[1]);
                mma_bf16(O[2 * nv + 1], pl, vh[2], vh[3]);
            }
        }
    }

    l0 += __shfl_xor_sync(0xFFFFFFFF, l0, 1);
    l0 += __shfl_xor_sync(0xFFFFFFFF, l0, 2);
    l1 += __shfl_xor_sync(0xFFFFFFFF, l1, 1);
    l1 += __shfl_xor_sync(0xFFFFFFFF, l1, 2);
    const float inv0 = 1.f / l0, inv1 = 1.f / l1;
    const int gq = lane >> 2, tig = lane & 3;
    const int qs0 = token_of(t, w * 16 + gq);
    const int qs1 = token_of(t, w * 16 + gq + 8);
    const size_t r0 = base + (size_t)qs0 * NHD;
    const size_t r1 = base + (size_t)qs1 * NHD;
#pragma unroll
    for (int nf = 0; nf < 8; nf++) {
        const int col = nf * 8 + tig * 2;
        *(float2*)&Att[r0 + col] = make_float2(rna_tf32(O[nf][0] * inv0),
                                               rna_tf32(O[nf][1] * inv0));
        *(float2*)&Att[r1 + col] = make_float2(rna_tf32(O[nf][2] * inv1),
                                               rna_tf32(O[nf][3] * inv1));
    }
}

// ---------------------------------------------------------------------------
// Launch
// ---------------------------------------------------------------------------
extern "C" void kernel_launch(void* const* d_in, const int* in_sizes, int n_in,
                              void* d_out, int out_size)
{
    const float* hs = (const float*)d_in[0];
    const float* Wq = (const float*)d_in[1];
    const float* Wk = (const float*)d_in[2];
    const float* Wv = (const float*)d_in[3];
    const float* Wo = (const float*)d_in[4];
    float* out = (float*)d_out;

    float *hst, *wt, *q, *k, *att;
    __nv_bfloat16 *vhi, *vlo;
    cudaGetSymbolAddress((void**)&hst, g_hst);
    cudaGetSymbolAddress((void**)&wt, g_wt);
    cudaGetSymbolAddress((void**)&q, g_q);
    cudaGetSymbolAddress((void**)&k, g_k);
    cudaGetSymbolAddress((void**)&att, g_att);
    cudaGetSymbolAddress((void**)&vhi, g_vhi);
    cudaGetSymbolAddress((void**)&vlo, g_vlo);

    cudaFuncSetAttribute(qkv_tf32_kernel, cudaFuncAttributeMaxDynamicSharedMemorySize, GEMM_SMEM);
    cudaFuncSetAttribute(out_tf32_kernel, cudaFuncAttributeMaxDynamicSharedMemorySize, GEMM_SMEM);
    cudaFuncSetAttribute(attn_mma_kernel, cudaFuncAttributeMaxDynamicSharedMemorySize, ATT_SMEM);

    const int n4 = (M_ROWS * HID) / 4;
    hsround_kernel<<<(n4 + 255) / 256, 256>>>(hs, hst, n4);
    wt_kernel<<<dim3(NHD / 32, HID / 32, 4), dim3(32, 8)>>>(Wq, Wk, Wv, Wo, wt);

    qkv_tf32_kernel<<<dim3(NHD / 128, M_ROWS / 128, 3), 128, GEMM_SMEM>>>(
        hst, wt, q, k, vhi, vlo);

    attn_mma_kernel<<<dim3(NT, NH, B_SZ), 256, ATT_SMEM>>>(q, k, vhi, vlo, att);

    const size_t WSZ = (size_t)HID * NHD;
    out_tf32_kernel<<<dim3(HID / 128, M_ROWS / 128), 128, GEMM_SMEM>>>(
        att, wt + 3 * WSZ, out);
}

// round 16
// speedup vs baseline: 3.6574x; 1.5689x over previous
#include <cuda_runtime.h>
#include <cuda_fp16.h>
#include <cstdint>
#include <cstddef>

// ---------------------------------------------------------------------------
// Problem constants
// ---------------------------------------------------------------------------
#define B_SZ   2
#define S_SZ   4096
#define HID    2048
#define NH     32
#define HD     64
#define NHD    2048
#define M_ROWS (B_SZ * S_SZ)       // 8192
#define NT     32
#define NKV    4
#define SCALE_F 0.125f
#define KDIM   2048

// ---------------------------------------------------------------------------
// PTX helpers (plain sm_80+ features only)
// ---------------------------------------------------------------------------
__device__ __forceinline__ uint32_t smem_u32(const void* p) {
    uint32_t a;
    asm("{ .reg .u64 t; cvta.to.shared.u64 t, %1; cvt.u32.u64 %0, t; }" : "=r"(a) : "l"(p));
    return a;
}
#define CP_ASYNC16(dst, src) \
    asm volatile("cp.async.cg.shared.global [%0], [%1], 16;" :: "r"(dst), "l"(src) : "memory")
#define CP_COMMIT()  asm volatile("cp.async.commit_group;" ::: "memory")
#define CP_WAIT(n)   asm volatile("cp.async.wait_group %0;" :: "n"(n) : "memory")

__device__ __forceinline__ void ldm4(uint32_t* r, uint32_t addr) {
    asm volatile("ldmatrix.sync.aligned.m8n8.x4.shared.b16 {%0,%1,%2,%3}, [%4];"
        : "=r"(r[0]), "=r"(r[1]), "=r"(r[2]), "=r"(r[3]) : "r"(addr));
}
__device__ __forceinline__ void ldm4t(uint32_t* r, uint32_t addr) {
    asm volatile("ldmatrix.sync.aligned.m8n8.x4.trans.shared.b16 {%0,%1,%2,%3}, [%4];"
        : "=r"(r[0]), "=r"(r[1]), "=r"(r[2]), "=r"(r[3]) : "r"(addr));
}
__device__ __forceinline__ void mma_fp16(float* d, const uint32_t* a, uint32_t b0, uint32_t b1) {
    asm volatile("mma.sync.aligned.m16n8k16.row.col.f32.f16.f16.f32 "
        "{%0,%1,%2,%3}, {%4,%5,%6,%7}, {%8,%9}, {%0,%1,%2,%3};"
        : "+f"(d[0]), "+f"(d[1]), "+f"(d[2]), "+f"(d[3])
        : "r"(a[0]), "r"(a[1]), "r"(a[2]), "r"(a[3]), "r"(b0), "r"(b1));
}
__device__ __forceinline__ uint32_t pkh(float a, float b) {
    const __half2 t = __floats2half2_rn(a, b);
    return *(const uint32_t*)&t;
}

// ---------------------------------------------------------------------------
// Scratch (device globals)
// ---------------------------------------------------------------------------
__device__ __half g_hsh[M_ROWS * HID];             // hs, fp16
__device__ __half g_wt[4 * HID * NHD];             // W^T [N][K], fp16
__device__ __half g_q[M_ROWS * NHD];               // Q (scaled), fp16
__device__ __half g_k[M_ROWS * NHD];               // K, fp16
__device__ __half g_v[M_ROWS * NHD];               // V, fp16
__device__ __half g_att[M_ROWS * NHD];             // attention out, fp16

// ---------------------------------------------------------------------------
// Pre-pass 1: hs -> fp16
// ---------------------------------------------------------------------------
__global__ void hsh_kernel(const float* __restrict__ x, __half* __restrict__ y, int n4)
{
    int i = blockIdx.x * blockDim.x + threadIdx.x;
    if (i >= n4) return;
    const float4 v = ((const float4*)x)[i];
    ((__half2*)y)[i * 2]     = __floats2half2_rn(v.x, v.y);
    ((__half2*)y)[i * 2 + 1] = __floats2half2_rn(v.z, v.w);
}

// ---------------------------------------------------------------------------
// Pre-pass 2: W[K,N] -> Wt[N,K] fp16 (32x32 smem tiles)
// ---------------------------------------------------------------------------
__global__ void wt_kernel(const float* __restrict__ W0, const float* __restrict__ W1,
                          const float* __restrict__ W2, const float* __restrict__ W3,
                          __half* __restrict__ wt)
{
    const int z = blockIdx.z;
    const float* W = (z == 0) ? W0 : (z == 1) ? W1 : (z == 2) ? W2 : W3;
    __shared__ float t[32][33];
    const int n0 = blockIdx.x * 32, k0 = blockIdx.y * 32;
    const int tx = threadIdx.x, ty = threadIdx.y;
#pragma unroll
    for (int i = 0; i < 4; i++)
        t[ty + 8 * i][tx] = W[(size_t)(k0 + ty + 8 * i) * NHD + n0 + tx];
    __syncthreads();
    const size_t zo = (size_t)z * HID * NHD;
#pragma unroll
    for (int i = 0; i < 4; i++)
        wt[zo + (size_t)(n0 + ty + 8 * i) * KDIM + k0 + tx] = __float2half_rn(t[tx][ty + 8 * i]);
}

// ---------------------------------------------------------------------------
// Single-pass fp16 GEMM: C[M,N] = A[M,K] @ B[N,K]^T.
// CTA 128x128, 4 warps (64x64), BK=32, 2-stage cp.async, 40KB smem.
// Epilogue modes: 0 = fp32 store, 1 = fp16 store (* cscale).
// ---------------------------------------------------------------------------
#define BK        32
#define NITER     (KDIM / BK)           // 64
#define STR_B     80                    // 32 fp16 = 64B + 16B pad
#define MAT_B     (128 * STR_B)         // 10240
#define OFF_A     0
#define OFF_B     MAT_B
#define STAGE_B   (2 * MAT_B)           // 20480
#define GEMM_SMEM (2 * STAGE_B)         // 40960

struct GemmPtrs {
    const __half *A, *B;
    float* C;
    __half* Ch;
    float cscale;
};

__device__ __forceinline__ void gemm_copy_stage(
    uint32_t sdst, const GemmPtrs& g, int m0, int n0, int kb, int tid)
{
#pragma unroll
    for (int i = 0; i < 8; i++) {
        const int idx = tid + i * 128;
        const int mat = idx >> 9, rem = idx & 511;
        const int row = rem >> 2, c = rem & 3;
        const __half* sp = (mat == 0)
            ? g.A + (size_t)(m0 + row) * KDIM + kb + c * 8
            : g.B + (size_t)(n0 + row) * KDIM + kb + c * 8;
        CP_ASYNC16(sdst + mat * MAT_B + row * STR_B + c * 16, sp);
    }
    CP_COMMIT();
}

template <int MODE>
__device__ __forceinline__ void gemm_body_fp16(const GemmPtrs& g)
{
    extern __shared__ __align__(128) char smem[];
    const uint32_t sbase = smem_u32(smem);
    const int tid = threadIdx.x, wid = tid >> 5, lane = tid & 31;
    const int m0 = blockIdx.y * 128, n0 = blockIdx.x * 128;
    const int wm = wid & 1, wn = wid >> 1;

    float acc[4][8][4];
#pragma unroll
    for (int a = 0; a < 4; a++)
#pragma unroll
        for (int b = 0; b < 8; b++)
#pragma unroll
            for (int c = 0; c < 4; c++) acc[a][b][c] = 0.f;

    const uint32_t lofs = (uint32_t)((lane & 15) * STR_B + (lane >> 4) * 16);

    gemm_copy_stage(sbase, g, m0, n0, 0, tid);

    for (int t = 0; t < NITER; ++t) {
        if (t + 1 < NITER) {
            gemm_copy_stage(sbase + ((t + 1) & 1) * STAGE_B, g, m0, n0, (t + 1) * BK, tid);
            CP_WAIT(1);
        } else {
            CP_WAIT(0);
        }
        __syncthreads();

        const uint32_t s0 = sbase + (t & 1) * STAGE_B;
#pragma unroll
        for (int ks = 0; ks < 2; ++ks) {
            const uint32_t aoff = s0 + OFF_A + (uint32_t)(wm * 64 * STR_B + ks * 32) + lofs;
            uint32_t Af[16];
#pragma unroll
            for (int mf = 0; mf < 4; mf++)
                ldm4(Af + mf * 4, aoff + mf * 16 * STR_B);
#pragma unroll
            for (int half = 0; half < 2; half++) {
                const uint32_t boff = s0 + OFF_B +
                    (uint32_t)((wn * 64 + half * 32) * STR_B + ks * 32) + lofs;
                uint32_t Bf[8];
                ldm4(Bf + 0, boff);
                ldm4(Bf + 4, boff + 16 * STR_B);
#pragma unroll
                for (int mf = 0; mf < 4; mf++)
#pragma unroll
                    for (int nl = 0; nl < 4; nl++) {
                        const uint32_t b0i = (nl >> 1) * 4 + (nl & 1);
                        mma_fp16(acc[mf][half * 4 + nl], Af + mf * 4, Bf[b0i], Bf[b0i + 2]);
                    }
            }
        }
        __syncthreads();
    }

    const int gq = lane >> 2, tig = lane & 3;
#pragma unroll
    for (int mf = 0; mf < 4; mf++) {
        const int row = m0 + wm * 64 + mf * 16 + gq;
#pragma unroll
        for (int nf = 0; nf < 8; nf++) {
            const int col = n0 + wn * 64 + nf * 8 + tig * 2;
            if (MODE == 1) {
#pragma unroll
                for (int half = 0; half < 2; half++) {
                    const size_t off = (size_t)(row + half * 8) * 2048 + col;
                    *(__half2*)&g.Ch[off] = __floats2half2_rn(
                        acc[mf][nf][half * 2] * g.cscale,
                        acc[mf][nf][half * 2 + 1] * g.cscale);
                }
            } else {
                *(float2*)&g.C[(size_t)row * 2048 + col] =
                    make_float2(acc[mf][nf][0], acc[mf][nf][1]);
                *(float2*)&g.C[(size_t)(row + 8) * 2048 + col] =
                    make_float2(acc[mf][nf][2], acc[mf][nf][3]);
            }
        }
    }
}

__global__ __launch_bounds__(128, 2) void qkv_fp16_kernel(
    const __half* __restrict__ A, const __half* __restrict__ Wt,
    __half* __restrict__ Q, __half* __restrict__ K, __half* __restrict__ V)
{
    const size_t WSZ = (size_t)HID * NHD;
    const int z = blockIdx.z;
    GemmPtrs g;
    g.A = A;
    g.B = Wt + (size_t)z * WSZ;
    g.C = nullptr;
    g.Ch = (z == 0) ? Q : (z == 1) ? K : V;
    g.cscale = (z == 0) ? SCALE_F : 1.0f;
    gemm_body_fp16<1>(g);
}

__global__ __launch_bounds__(128, 2) void out_fp16_kernel(
    const __half* __restrict__ A, const __half* __restrict__ Wt, float* __restrict__ C)
{
    GemmPtrs g;
    g.A = A; g.B = Wt; g.C = C; g.Ch = nullptr; g.cscale = 1.0f;
    gemm_body_fp16<0>(g);
}

// ---------------------------------------------------------------------------
// Flash attention, single-pass fp16 QK and PV.
// Row stride 144B = 64 fp16 (128B) + 16B pad (odd 16B stride: conflict-free).
// Tiles: Q/K/V 128 x 144B = 18432B each; total 54KB.
// ---------------------------------------------------------------------------
#define ASTR    144
#define AQ_O    0
#define AK_O    18432
#define AV_O    36864
#define ATT_SMEM 55296

__device__ __forceinline__ int token_of(int tile, int jj)
{
    return ((tile >> 2) << 9) + ((jj >> 4) << 6) + ((tile & 3) << 4) + (jj & 15);
}

__global__ __launch_bounds__(256, 1) void attn_mma_kernel(
    const __half* __restrict__ Qg, const __half* __restrict__ Kg,
    const __half* __restrict__ Vg, __half* __restrict__ Att)
{
    extern __shared__ __align__(128) char smem[];
    const uint32_t sbase = smem_u32(smem);
    const int t = blockIdx.x, h = blockIdx.y, b = blockIdx.z;
    const int tid = threadIdx.x, w = tid >> 5, lane = tid & 31;
    const size_t base = (size_t)b * S_SZ * NHD + (size_t)h * HD;

    const int tr = t >> 2, tc = t & 3;
    const int cr = min(max(tr, 1), 7);
    const int cc = min(max(tc, 1), 3);
    int kts[NKV];
    kts[0] = (cr - 1) * 4 + (cc - 1);
    kts[1] = (cr - 1) * 4 + cc;
    kts[2] = cr * 4 + (cc - 1);
    kts[3] = cr * 4 + cc;

    // Q tile: 128 rows x 8 chunks (64 fp16 = 128B per row)
    for (int i = tid; i < 1024; i += 256) {
        const int row = i >> 3, c = i & 7;
        const int qs = token_of(t, row);
        CP_ASYNC16(sbase + AQ_O + row * ASTR + c * 16, Qg + base + (size_t)qs * NHD + c * 8);
    }
    CP_COMMIT();
    CP_WAIT(0);
    __syncthreads();

    // Q fragments: 4 k16-steps, resident for all kv tiles
    uint32_t qf[4][4];
    const uint32_t lofs = (uint32_t)((lane & 15) * ASTR + (lane >> 4) * 16);
    const uint32_t qrow = (uint32_t)(w * 16 * ASTR);
#pragma unroll
    for (int kf = 0; kf < 4; kf++)
        ldm4(qf[kf], sbase + AQ_O + qrow + kf * 32 + lofs);

    float O[8][4];
#pragma unroll
    for (int nf = 0; nf < 8; nf++)
#pragma unroll
        for (int c = 0; c < 4; c++) O[nf][c] = 0.f;
    float m0 = -1e30f, m1 = -1e30f, l0 = 0.f, l1 = 0.f;

    for (int w4 = 0; w4 < NKV; ++w4) {
        const int kt = kts[w4];
        __syncthreads();
        // K + V tiles: 1024 chunks each (128 rows x 8)
        for (int i = tid; i < 2048; i += 256) {
            const int sel = i >> 10, rem = i & 1023;
            const int row = rem >> 3, c = rem & 7;
            const int ks = token_of(kt, row);
            const __half* src = (sel ? Vg : Kg) + base + (size_t)ks * NHD + c * 8;
            CP_ASYNC16(sbase + (sel ? AV_O : AK_O) + row * ASTR + c * 16, src);
        }
        CP_COMMIT();
        CP_WAIT(0);
        __syncthreads();

        // ---- S = Q @ K^T, fp16 (scale folded into Q) ----
        float S[16][4];
#pragma unroll
        for (int nf = 0; nf < 16; nf++)
#pragma unroll
            for (int c = 0; c < 4; c++) S[nf][c] = 0.f;

#pragma unroll
        for (int kf = 0; kf < 4; kf++) {
#pragma unroll
            for (int g = 0; g < 8; g++) {
                uint32_t kh[4];
                ldm4(kh, sbase + AK_O + (uint32_t)(g * 16 * ASTR) + kf * 32 + lofs);
                mma_fp16(S[2 * g],     qf[kf], kh[0], kh[2]);
                mma_fp16(S[2 * g + 1], qf[kf], kh[1], kh[3]);
            }
        }

        // ---- online softmax ----
        float tmax0 = -1e30f, tmax1 = -1e30f;
#pragma unroll
        for (int nf = 0; nf < 16; nf++) {
            tmax0 = fmaxf(tmax0, fmaxf(S[nf][0], S[nf][1]));
            tmax1 = fmaxf(tmax1, fmaxf(S[nf][2], S[nf][3]));
        }
        tmax0 = fmaxf(tmax0, __shfl_xor_sync(0xFFFFFFFF, tmax0, 1));
        tmax0 = fmaxf(tmax0, __shfl_xor_sync(0xFFFFFFFF, tmax0, 2));
        tmax1 = fmaxf(tmax1, __shfl_xor_sync(0xFFFFFFFF, tmax1, 1));
        tmax1 = fmaxf(tmax1, __shfl_xor_sync(0xFFFFFFFF, tmax1, 2));

        const float mn0 = fmaxf(m0, tmax0), mn1 = fmaxf(m1, tmax1);
        const float a0 = __expf(m0 - mn0), a1 = __expf(m1 - mn1);
        m0 = mn0; m1 = mn1;
        l0 *= a0; l1 *= a1;
#pragma unroll
        for (int nf = 0; nf < 8; nf++) {
            O[nf][0] *= a0; O[nf][1] *= a0;
            O[nf][2] *= a1; O[nf][3] *= a1;
        }
        float ls0 = 0.f, ls1 = 0.f;
#pragma unroll
        for (int nf = 0; nf < 16; nf++) {
            S[nf][0] = __expf(S[nf][0] - m0); ls0 += S[nf][0];
            S[nf][1] = __expf(S[nf][1] - m0); ls0 += S[nf][1];
            S[nf][2] = __expf(S[nf][2] - m1); ls1 += S[nf][2];
            S[nf][3] = __expf(S[nf][3] - m1); ls1 += S[nf][3];
        }
        l0 += ls0; l1 += ls1;

        // ---- O += P @ V, single-pass fp16 ----
#pragma unroll
        for (int kf = 0; kf < 8; kf++) {
            uint32_t ph[4];
            ph[0] = pkh(S[2 * kf][0],     S[2 * kf][1]);
            ph[1] = pkh(S[2 * kf][2],     S[2 * kf][3]);
            ph[2] = pkh(S[2 * kf + 1][0], S[2 * kf + 1][1]);
            ph[3] = pkh(S[2 * kf + 1][2], S[2 * kf + 1][3]);
#pragma unroll
            for (int nv = 0; nv < 4; nv++) {
                uint32_t vh[4];
                const uint32_t vo = (uint32_t)((kf * 16 + (lane & 15)) * ASTR +
                                               (lane >> 4) * 16 + nv * 32);
                ldm4t(vh, sbase + AV_O + vo);
                mma_fp16(O[2 * nv],     ph, vh[0], vh[1]);
                mma_fp16(O[2 * nv + 1], ph, vh[2], vh[3]);
            }
        }
    }

    l0 += __shfl_xor_sync(0xFFFFFFFF, l0, 1);
    l0 += __shfl_xor_sync(0xFFFFFFFF, l0, 2);
    l1 += __shfl_xor_sync(0xFFFFFFFF, l1, 1);
    l1 += __shfl_xor_sync(0xFFFFFFFF, l1, 2);
    const float inv0 = 1.f / l0, inv1 = 1.f / l1;
    const int gq = lane >> 2, tig = lane & 3;
    const int qs0 = token_of(t, w * 16 + gq);
    const int qs1 = token_of(t, w * 16 + gq + 8);
    const size_t r0 = base + (size_t)qs0 * NHD;
    const size_t r1 = base + (size_t)qs1 * NHD;
#pragma unroll
    for (int nf = 0; nf < 8; nf++) {
        const int col = nf * 8 + tig * 2;
        *(__half2*)&Att[r0 + col] = __floats2half2_rn(O[nf][0] * inv0, O[nf][1] * inv0);
        *(__half2*)&Att[r1 + col] = __floats2half2_rn(O[nf][2] * inv1, O[nf][3] * inv1);
    }
}

// ---------------------------------------------------------------------------
// Launch
// ---------------------------------------------------------------------------
extern "C" void kernel_launch(void* const* d_in, const int* in_sizes, int n_in,
                              void* d_out, int out_size)
{
    const float* hs = (const float*)d_in[0];
    const float* Wq = (const float*)d_in[1];
    const float* Wk = (const float*)d_in[2];
    const float* Wv = (const float*)d_in[3];
    const float* Wo = (const float*)d_in[4];
    float* out = (float*)d_out;

    __half *hsh, *wt, *q, *k, *v, *att;
    cudaGetSymbolAddress((void**)&hsh, g_hsh);
    cudaGetSymbolAddress((void**)&wt, g_wt);
    cudaGetSymbolAddress((void**)&q, g_q);
    cudaGetSymbolAddress((void**)&k, g_k);
    cudaGetSymbolAddress((void**)&v, g_v);
    cudaGetSymbolAddress((void**)&att, g_att);

    cudaFuncSetAttribute(qkv_fp16_kernel, cudaFuncAttributeMaxDynamicSharedMemorySize, GEMM_SMEM);
    cudaFuncSetAttribute(out_fp16_kernel, cudaFuncAttributeMaxDynamicSharedMemorySize, GEMM_SMEM);
    cudaFuncSetAttribute(attn_mma_kernel, cudaFuncAttributeMaxDynamicSharedMemorySize, ATT_SMEM);

    const int n4 = (M_ROWS * HID) / 4;
    hsh_kernel<<<(n4 + 255) / 256, 256>>>(hs, hsh, n4);
    wt_kernel<<<dim3(NHD / 32, HID / 32, 4), dim3(32, 8)>>>(Wq, Wk, Wv, Wo, wt);

    qkv_fp16_kernel<<<dim3(NHD / 128, M_ROWS / 128, 3), 128, GEMM_SMEM>>>(
        hsh, wt, q, k, v);

    attn_mma_kernel<<<dim3(NT, NH, B_SZ), 256, ATT_SMEM>>>(q, k, v, att);

    const size_t WSZ = (size_t)HID * NHD;
    out_fp16_kernel<<<dim3(HID / 128, M_ROWS / 128), 128, GEMM_SMEM>>>(
        att, wt + 3 * WSZ, out);
}

// round 17
// speedup vs baseline: 4.0895x; 1.1181x over previous
#include <cuda_runtime.h>
#include <cuda_fp16.h>
#include <cstdint>
#include <cstddef>

// ---------------------------------------------------------------------------
// Problem constants
// ---------------------------------------------------------------------------
#define B_SZ   2
#define S_SZ   4096
#define HID    2048
#define NH     32
#define HD     64
#define NHD    2048
#define M_ROWS (B_SZ * S_SZ)       // 8192
#define NT     32
#define NKV    4
#define SCALE_F 0.125f
#define KDIM   2048

// ---------------------------------------------------------------------------
// PTX helpers (plain sm_80+ features only)
// ---------------------------------------------------------------------------
__device__ __forceinline__ uint32_t smem_u32(const void* p) {
    uint32_t a;
    asm("{ .reg .u64 t; cvta.to.shared.u64 t, %1; cvt.u32.u64 %0, t; }" : "=r"(a) : "l"(p));
    return a;
}
#define CP_ASYNC16(dst, src) \
    asm volatile("cp.async.cg.shared.global [%0], [%1], 16;" :: "r"(dst), "l"(src) : "memory")
#define CP_COMMIT()  asm volatile("cp.async.commit_group;" ::: "memory")
#define CP_WAIT(n)   asm volatile("cp.async.wait_group %0;" :: "n"(n) : "memory")

__device__ __forceinline__ void ldm4(uint32_t* r, uint32_t addr) {
    asm volatile("ldmatrix.sync.aligned.m8n8.x4.shared.b16 {%0,%1,%2,%3}, [%4];"
        : "=r"(r[0]), "=r"(r[1]), "=r"(r[2]), "=r"(r[3]) : "r"(addr));
}
__device__ __forceinline__ void ldm4t(uint32_t* r, uint32_t addr) {
    asm volatile("ldmatrix.sync.aligned.m8n8.x4.trans.shared.b16 {%0,%1,%2,%3}, [%4];"
        : "=r"(r[0]), "=r"(r[1]), "=r"(r[2]), "=r"(r[3]) : "r"(addr));
}
__device__ __forceinline__ void mma_fp16(float* d, const uint32_t* a, uint32_t b0, uint32_t b1) {
    asm volatile("mma.sync.aligned.m16n8k16.row.col.f32.f16.f16.f32 "
        "{%0,%1,%2,%3}, {%4,%5,%6,%7}, {%8,%9}, {%0,%1,%2,%3};"
        : "+f"(d[0]), "+f"(d[1]), "+f"(d[2]), "+f"(d[3])
        : "r"(a[0]), "r"(a[1]), "r"(a[2]), "r"(a[3]), "r"(b0), "r"(b1));
}
__device__ __forceinline__ uint32_t pkh(float a, float b) {
    const __half2 t = __floats2half2_rn(a, b);
    return *(const uint32_t*)&t;
}

// ---------------------------------------------------------------------------
// Scratch (device globals)
// ---------------------------------------------------------------------------
__device__ __half g_hsh[M_ROWS * HID];             // hs, fp16
__device__ __half g_wt[4 * HID * NHD];             // W^T [N][K], fp16
__device__ __half g_q[M_ROWS * NHD];               // Q (scaled), fp16
__device__ __half g_k[M_ROWS * NHD];               // K, fp16
__device__ __half g_v[M_ROWS * NHD];               // V, fp16
__device__ __half g_att[M_ROWS * NHD];             // attention out, fp16

// ---------------------------------------------------------------------------
// Pre-pass 1: hs -> fp16
// ---------------------------------------------------------------------------
__global__ void hsh_kernel(const float* __restrict__ x, __half* __restrict__ y, int n4)
{
    int i = blockIdx.x * blockDim.x + threadIdx.x;
    if (i >= n4) return;
    const float4 v = ((const float4*)x)[i];
    ((__half2*)y)[i * 2]     = __floats2half2_rn(v.x, v.y);
    ((__half2*)y)[i * 2 + 1] = __floats2half2_rn(v.z, v.w);
}

// ---------------------------------------------------------------------------
// Pre-pass 2: W[K,N] -> Wt[N,K] fp16 (32x32 smem tiles)
// ---------------------------------------------------------------------------
__global__ void wt_kernel(const float* __restrict__ W0, const float* __restrict__ W1,
                          const float* __restrict__ W2, const float* __restrict__ W3,
                          __half* __restrict__ wt)
{
    const int z = blockIdx.z;
    const float* W = (z == 0) ? W0 : (z == 1) ? W1 : (z == 2) ? W2 : W3;
    __shared__ float t[32][33];
    const int n0 = blockIdx.x * 32, k0 = blockIdx.y * 32;
    const int tx = threadIdx.x, ty = threadIdx.y;
#pragma unroll
    for (int i = 0; i < 4; i++)
        t[ty + 8 * i][tx] = W[(size_t)(k0 + ty + 8 * i) * NHD + n0 + tx];
    __syncthreads();
    const size_t zo = (size_t)z * HID * NHD;
#pragma unroll
    for (int i = 0; i < 4; i++)
        wt[zo + (size_t)(n0 + ty + 8 * i) * KDIM + k0 + tx] = __float2half_rn(t[tx][ty + 8 * i]);
}

// ---------------------------------------------------------------------------
// Single-pass fp16 GEMM: C[M,N] = A[M,K] @ B[N,K]^T.
// CTA 128x128, 4 warps (64x64), BK=64 (one bar.sync per 128 MMA/warp),
// 2-stage cp.async, 72KB smem -> 2 CTAs/SM.
// ---------------------------------------------------------------------------
#define BK        64
#define NITER     (KDIM / BK)           // 32
#define STR_B     144                   // 64 fp16 = 128B + 16B pad
#define MAT_B     (128 * STR_B)         // 18432
#define OFF_A     0
#define OFF_B     MAT_B
#define STAGE_B   (2 * MAT_B)           // 36864
#define GEMM_SMEM (2 * STAGE_B)         // 73728

struct GemmPtrs {
    const __half *A, *B;
    float* C;
    __half* Ch;
    float cscale;
};

__device__ __forceinline__ void gemm_copy_stage(
    uint32_t sdst, const GemmPtrs& g, int m0, int n0, int kb, int tid)
{
    // 2048 x 16B chunks: A 1024 (128 rows x 8), B 1024; 16 per thread
#pragma unroll
    for (int i = 0; i < 16; i++) {
        const int idx = tid + i * 128;
        const int mat = idx >> 10, rem = idx & 1023;
        const int row = rem >> 3, c = rem & 7;
        const __half* sp = (mat == 0)
            ? g.A + (size_t)(m0 + row) * KDIM + kb + c * 8
            : g.B + (size_t)(n0 + row) * KDIM + kb + c * 8;
        CP_ASYNC16(sdst + mat * MAT_B + row * STR_B + c * 16, sp);
    }
    CP_COMMIT();
}

template <int MODE>
__device__ __forceinline__ void gemm_body_fp16(const GemmPtrs& g)
{
    extern __shared__ __align__(128) char smem[];
    const uint32_t sbase = smem_u32(smem);
    const int tid = threadIdx.x, wid = tid >> 5, lane = tid & 31;
    const int m0 = blockIdx.y * 128, n0 = blockIdx.x * 128;
    const int wm = wid & 1, wn = wid >> 1;

    float acc[4][8][4];
#pragma unroll
    for (int a = 0; a < 4; a++)
#pragma unroll
        for (int b = 0; b < 8; b++)
#pragma unroll
            for (int c = 0; c < 4; c++) acc[a][b][c] = 0.f;

    const uint32_t lofs = (uint32_t)((lane & 15) * STR_B + (lane >> 4) * 16);

    gemm_copy_stage(sbase, g, m0, n0, 0, tid);

    for (int t = 0; t < NITER; ++t) {
        if (t + 1 < NITER) {
            gemm_copy_stage(sbase + ((t + 1) & 1) * STAGE_B, g, m0, n0, (t + 1) * BK, tid);
            CP_WAIT(1);
        } else {
            CP_WAIT(0);
        }
        __syncthreads();

        const uint32_t s0 = sbase + (t & 1) * STAGE_B;
#pragma unroll
        for (int ks = 0; ks < 4; ++ks) {          // 4 x k16 within BK=64
            const uint32_t aoff = s0 + OFF_A + (uint32_t)(wm * 64 * STR_B + ks * 32) + lofs;
            uint32_t Af[16];
#pragma unroll
            for (int mf = 0; mf < 4; mf++)
                ldm4(Af + mf * 4, aoff + mf * 16 * STR_B);
#pragma unroll
            for (int half = 0; half < 2; half++) {
                const uint32_t boff = s0 + OFF_B +
                    (uint32_t)((wn * 64 + half * 32) * STR_B + ks * 32) + lofs;
                uint32_t Bf[8];
                ldm4(Bf + 0, boff);
                ldm4(Bf + 4, boff + 16 * STR_B);
#pragma unroll
                for (int mf = 0; mf < 4; mf++)
#pragma unroll
                    for (int nl = 0; nl < 4; nl++) {
                        const uint32_t b0i = (nl >> 1) * 4 + (nl & 1);
                        mma_fp16(acc[mf][half * 4 + nl], Af + mf * 4, Bf[b0i], Bf[b0i + 2]);
                    }
            }
        }
        __syncthreads();
    }

    const int gq = lane >> 2, tig = lane & 3;
#pragma unroll
    for (int mf = 0; mf < 4; mf++) {
        const int row = m0 + wm * 64 + mf * 16 + gq;
#pragma unroll
        for (int nf = 0; nf < 8; nf++) {
            const int col = n0 + wn * 64 + nf * 8 + tig * 2;
            if (MODE == 1) {
#pragma unroll
                for (int half = 0; half < 2; half++) {
                    const size_t off = (size_t)(row + half * 8) * 2048 + col;
                    *(__half2*)&g.Ch[off] = __floats2half2_rn(
                        acc[mf][nf][half * 2] * g.cscale,
                        acc[mf][nf][half * 2 + 1] * g.cscale);
                }
            } else {
                *(float2*)&g.C[(size_t)row * 2048 + col] =
                    make_float2(acc[mf][nf][0], acc[mf][nf][1]);
                *(float2*)&g.C[(size_t)(row + 8) * 2048 + col] =
                    make_float2(acc[mf][nf][2], acc[mf][nf][3]);
            }
        }
    }
}

__global__ __launch_bounds__(128, 2) void qkv_fp16_kernel(
    const __half* __restrict__ A, const __half* __restrict__ Wt,
    __half* __restrict__ Q, __half* __restrict__ K, __half* __restrict__ V)
{
    const size_t WSZ = (size_t)HID * NHD;
    const int z = blockIdx.z;
    GemmPtrs g;
    g.A = A;
    g.B = Wt + (size_t)z * WSZ;
    g.C = nullptr;
    g.Ch = (z == 0) ? Q : (z == 1) ? K : V;
    g.cscale = (z == 0) ? SCALE_F : 1.0f;
    gemm_body_fp16<1>(g);
}

__global__ __launch_bounds__(128, 2) void out_fp16_kernel(
    const __half* __restrict__ A, const __half* __restrict__ Wt, float* __restrict__ C)
{
    GemmPtrs g;
    g.A = A; g.B = Wt; g.C = C; g.Ch = nullptr; g.cscale = 1.0f;
    gemm_body_fp16<0>(g);
}

// ---------------------------------------------------------------------------
// Flash attention, single-pass fp16 QK and PV (R16-validated).
// Row stride 144B = 64 fp16 + 16B pad; Q/K/V tiles 18432B; total 54KB.
// ---------------------------------------------------------------------------
#define ASTR    144
#define AQ_O    0
#define AK_O    18432
#define AV_O    36864
#define ATT_SMEM 55296

__device__ __forceinline__ int token_of(int tile, int jj)
{
    return ((tile >> 2) << 9) + ((jj >> 4) << 6) + ((tile & 3) << 4) + (jj & 15);
}

__global__ __launch_bounds__(256, 1) void attn_mma_kernel(
    const __half* __restrict__ Qg, const __half* __restrict__ Kg,
    const __half* __restrict__ Vg, __half* __restrict__ Att)
{
    extern __shared__ __align__(128) char smem[];
    const uint32_t sbase = smem_u32(smem);
    const int t = blockIdx.x, h = blockIdx.y, b = blockIdx.z;
    const int tid = threadIdx.x, w = tid >> 5, lane = tid & 31;
    const size_t base = (size_t)b * S_SZ * NHD + (size_t)h * HD;

    const int tr = t >> 2, tc = t & 3;
    const int cr = min(max(tr, 1), 7);
    const int cc = min(max(tc, 1), 3);
    int kts[NKV];
    kts[0] = (cr - 1) * 4 + (cc - 1);
    kts[1] = (cr - 1) * 4 + cc;
    kts[2] = cr * 4 + (cc - 1);
    kts[3] = cr * 4 + cc;

    for (int i = tid; i < 1024; i += 256) {
        const int row = i >> 3, c = i & 7;
        const int qs = token_of(t, row);
        CP_ASYNC16(sbase + AQ_O + row * ASTR + c * 16, Qg + base + (size_t)qs * NHD + c * 8);
    }
    CP_COMMIT();
    CP_WAIT(0);
    __syncthreads();

    uint32_t qf[4][4];
    const uint32_t lofs = (uint32_t)((lane & 15) * ASTR + (lane >> 4) * 16);
    const uint32_t qrow = (uint32_t)(w * 16 * ASTR);
#pragma unroll
    for (int kf = 0; kf < 4; kf++)
        ldm4(qf[kf], sbase + AQ_O + qrow + kf * 32 + lofs);

    float O[8][4];
#pragma unroll
    for (int nf = 0; nf < 8; nf++)
#pragma unroll
        for (int c = 0; c < 4; c++) O[nf][c] = 0.f;
    float m0 = -1e30f, m1 = -1e30f, l0 = 0.f, l1 = 0.f;

    for (int w4 = 0; w4 < NKV; ++w4) {
        const int kt = kts[w4];
        __syncthreads();
        for (int i = tid; i < 2048; i += 256) {
            const int sel = i >> 10, rem = i & 1023;
            const int row = rem >> 3, c = rem & 7;
            const int ks = token_of(kt, row);
            const __half* src = (sel ? Vg : Kg) + base + (size_t)ks * NHD + c * 8;
            CP_ASYNC16(sbase + (sel ? AV_O : AK_O) + row * ASTR + c * 16, src);
        }
        CP_COMMIT();
        CP_WAIT(0);
        __syncthreads();

        // ---- S = Q @ K^T, fp16 (scale folded into Q) ----
        float S[16][4];
#pragma unroll
        for (int nf = 0; nf < 16; nf++)
#pragma unroll
            for (int c = 0; c < 4; c++) S[nf][c] = 0.f;

#pragma unroll
        for (int kf = 0; kf < 4; kf++) {
#pragma unroll
            for (int g = 0; g < 8; g++) {
                uint32_t kh[4];
                ldm4(kh, sbase + AK_O + (uint32_t)(g * 16 * ASTR) + kf * 32 + lofs);
                mma_fp16(S[2 * g],     qf[kf], kh[0], kh[2]);
                mma_fp16(S[2 * g + 1], qf[kf], kh[1], kh[3]);
            }
        }

        // ---- online softmax ----
        float tmax0 = -1e30f, tmax1 = -1e30f;
#pragma unroll
        for (int nf = 0; nf < 16; nf++) {
            tmax0 = fmaxf(tmax0, fmaxf(S[nf][0], S[nf][1]));
            tmax1 = fmaxf(tmax1, fmaxf(S[nf][2], S[nf][3]));
        }
        tmax0 = fmaxf(tmax0, __shfl_xor_sync(0xFFFFFFFF, tmax0, 1));
        tmax0 = fmaxf(tmax0, __shfl_xor_sync(0xFFFFFFFF, tmax0, 2));
        tmax1 = fmaxf(tmax1, __shfl_xor_sync(0xFFFFFFFF, tmax1, 1));
        tmax1 = fmaxf(tmax1, __shfl_xor_sync(0xFFFFFFFF, tmax1, 2));

        const float mn0 = fmaxf(m0, tmax0), mn1 = fmaxf(m1, tmax1);
        const float a0 = __expf(m0 - mn0), a1 = __expf(m1 - mn1);
        m0 = mn0; m1 = mn1;
        l0 *= a0; l1 *= a1;
#pragma unroll
        for (int nf = 0; nf < 8; nf++) {
            O[nf][0] *= a0; O[nf][1] *= a0;
            O[nf][2] *= a1; O[nf][3] *= a1;
        }
        float ls0 = 0.f, ls1 = 0.f;
#pragma unroll
        for (int nf = 0; nf < 16; nf++) {
            S[nf][0] = __expf(S[nf][0] - m0); ls0 += S[nf][0];
            S[nf][1] = __expf(S[nf][1] - m0); ls0 += S[nf][1];
            S[nf][2] = __expf(S[nf][2] - m1); ls1 += S[nf][2];
            S[nf][3] = __expf(S[nf][3] - m1); ls1 += S[nf][3];
        }
        l0 += ls0; l1 += ls1;

        // ---- O += P @ V, single-pass fp16 ----
#pragma unroll
        for (int kf = 0; kf < 8; kf++) {
            uint32_t ph[4];
            ph[0] = pkh(S[2 * kf][0],     S[2 * kf][1]);
            ph[1] = pkh(S[2 * kf][2],     S[2 * kf][3]);
            ph[2] = pkh(S[2 * kf + 1][0], S[2 * kf + 1][1]);
            ph[3] = pkh(S[2 * kf + 1][2], S[2 * kf + 1][3]);
#pragma unroll
            for (int nv = 0; nv < 4; nv++) {
                uint32_t vh[4];
                const uint32_t vo = (uint32_t)((kf * 16 + (lane & 15)) * ASTR +
                                               (lane >> 4) * 16 + nv * 32);
                ldm4t(vh, sbase + AV_O + vo);
                mma_fp16(O[2 * nv],     ph, vh[0], vh[1]);
                mma_fp16(O[2 * nv + 1], ph, vh[2], vh[3]);
            }
        }
    }

    l0 += __shfl_xor_sync(0xFFFFFFFF, l0, 1);
    l0 += __shfl_xor_sync(0xFFFFFFFF, l0, 2);
    l1 += __shfl_xor_sync(0xFFFFFFFF, l1, 1);
    l1 += __shfl_xor_sync(0xFFFFFFFF, l1, 2);
    const float inv0 = 1.f / l0, inv1 = 1.f / l1;
    const int gq = lane >> 2, tig = lane & 3;
    const int qs0 = token_of(t, w * 16 + gq);
    const int qs1 = token_of(t, w * 16 + gq + 8);
    const size_t r0 = base + (size_t)qs0 * NHD;
    const size_t r1 = base + (size_t)qs1 * NHD;
#pragma unroll
    for (int nf = 0; nf < 8; nf++) {
        const int col = nf * 8 + tig * 2;
        *(__half2*)&Att[r0 + col] = __floats2half2_rn(O[nf][0] * inv0, O[nf][1] * inv0);
        *(__half2*)&Att[r1 + col] = __floats2half2_rn(O[nf][2] * inv1, O[nf][3] * inv1);
    }
}

// ---------------------------------------------------------------------------
// Launch
// ---------------------------------------------------------------------------
extern "C" void kernel_launch(void* const* d_in, const int* in_sizes, int n_in,
                              void* d_out, int out_size)
{
    const float* hs = (const float*)d_in[0];
    const float* Wq = (const float*)d_in[1];
    const float* Wk = (const float*)d_in[2];
    const float* Wv = (const float*)d_in[3];
    const float* Wo = (const float*)d_in[4];
    float* out = (float*)d_out;

    __half *hsh, *wt, *q, *k, *v, *att;
    cudaGetSymbolAddress((void**)&hsh, g_hsh);
    cudaGetSymbolAddress((void**)&wt, g_wt);
    cudaGetSymbolAddress((void**)&q, g_q);
    cudaGetSymbolAddress((void**)&k, g_k);
    cudaGetSymbolAddress((void**)&v, g_v);
    cudaGetSymbolAddress((void**)&att, g_att);

    cudaFuncSetAttribute(qkv_fp16_kernel, cudaFuncAttributeMaxDynamicSharedMemorySize, GEMM_SMEM);
    cudaFuncSetAttribute(out_fp16_kernel, cudaFuncAttributeMaxDynamicSharedMemorySize, GEMM_SMEM);
    cudaFuncSetAttribute(attn_mma_kernel, cudaFuncAttributeMaxDynamicSharedMemorySize, ATT_SMEM);

    const int n4 = (M_ROWS * HID) / 4;
    hsh_kernel<<<(n4 + 255) / 256, 256>>>(hs, hsh, n4);
    wt_kernel<<<dim3(NHD / 32, HID / 32, 4), dim3(32, 8)>>>(Wq, Wk, Wv, Wo, wt);

    qkv_fp16_kernel<<<dim3(NHD / 128, M_ROWS / 128, 3), 128, GEMM_SMEM>>>(
        hsh, wt, q, k, v);

    attn_mma_kernel<<<dim3(NT, NH, B_SZ), 256, ATT_SMEM>>>(q, k, v, att);

    const size_t WSZ = (size_t)HID * NHD;
    out_fp16_kernel<<<dim3(HID / 128, M_ROWS / 128), 128, GEMM_SMEM>>>(
        att, wt + 3 * WSZ, out);
}